// round 5
// baseline (speedup 1.0000x reference)
#include <cuda_runtime.h>
#include <math.h>

#define NB 4
#define NC 64
#define NO 64
#define NH 128
#define NW 128
#define HW (NH*NW)

typedef unsigned long long u64;

// ---- f32x2 packed helpers (sm_100+) ---------------------------------------
__device__ __forceinline__ u64 pack2(float lo, float hi) {
    u64 r; asm("mov.b64 %0, {%1, %2};" : "=l"(r) : "f"(lo), "f"(hi)); return r;
}
__device__ __forceinline__ u64 dup2(float v) {
    u64 r; asm("mov.b64 %0, {%1, %1};" : "=l"(r) : "f"(v)); return r;
}
__device__ __forceinline__ void unpack2(u64 p, float& lo, float& hi) {
    asm("mov.b64 {%0, %1}, %2;" : "=f"(lo), "=f"(hi) : "l"(p));
}
__device__ __forceinline__ u64 ffma2(u64 a, u64 b, u64 c) {
    u64 d; asm("fma.rn.f32x2 %0, %1, %2, %3;" : "=l"(d) : "l"(a), "l"(b), "l"(c)); return d;
}
__device__ __forceinline__ u64 fmul2(u64 a, u64 b) {
    u64 d; asm("mul.rn.f32x2 %0, %1, %2;" : "=l"(d) : "l"(a), "l"(b)); return d;
}
__device__ __forceinline__ void ldg128_2(const void* p, u64& lo, u64& hi) {
    asm("ld.global.nc.v2.u64 {%0,%1}, [%2];" : "=l"(lo), "=l"(hi) : "l"(p));
}
__device__ __forceinline__ void lds128_2(unsigned addr, u64& lo, u64& hi) {
    asm("ld.shared.v2.u64 {%0,%1}, [%2];" : "=l"(lo), "=l"(hi) : "r"(addr));
}

// Scratch (static device globals — no allocation)
__device__ float g_xT[NB*16*HW*4];      // x repacked: [b][c/4][h][w][4]
__device__ float g_py[NB*9*HW];         // sample y coord per (b,k,h,w)
__device__ float g_px[NB*9*HW];         // sample x coord
__device__ float g_ms[NB*9*HW];         // sigmoid(mask)
__device__ float g_Wt[9*64*64];         // weight repacked: [k][c][o]
__device__ float g_omwT[9*64*28];       // om_weight repacked: [tap][c][j(pad28)]

// ---------------------------------------------------------------------------
// Kernel 0: NCHW -> [b][c/4][h][w][4] repack (coalesced via smem tile)
// ---------------------------------------------------------------------------
__global__ void __launch_bounds__(256) k_transpose(const float* __restrict__ x) {
    __shared__ float ts[64][33];
    int blk = blockIdx.x;
    int wc = blk & 3;
    int h  = (blk >> 2) & 127;
    int b  = blk >> 9;
    int w0 = wc * 32;
    int t = threadIdx.x;
    #pragma unroll
    for (int i = 0; i < 8; i++) {
        int idx = i * 256 + t;
        int c = idx >> 5, w = idx & 31;
        ts[c][w] = x[((b*64 + c)*NH + h)*NW + w0 + w];
    }
    __syncthreads();
    #pragma unroll
    for (int i = 0; i < 8; i++) {
        int idx = i * 256 + t;
        int comp = idx & 3, w = (idx >> 2) & 31, cg = idx >> 7;
        g_xT[((((b*16 + cg)*NH + h)*NW + w0 + w) << 2) + comp] = ts[cg*4 + comp][w];
    }
}

// ---------------------------------------------------------------------------
// Kernel R: weight reorganizations.
// ---------------------------------------------------------------------------
__global__ void __launch_bounds__(256) k_reorg(const float* __restrict__ wgt,
                                               const float* __restrict__ omw) {
    int i = blockIdx.x * 256 + threadIdx.x;
    if (i < 9*64*64) {              // g_Wt[k][c][o] = weight[o][c][k]
        int o = i & 63, c = (i >> 6) & 63, k = i >> 12;
        g_Wt[i] = wgt[(o*64 + c)*9 + k];
    }
    if (i < 9*64*28) {              // g_omwT[tap][c][j] = om_weight[j][c][tap]
        int j = i % 28;
        int c = (i / 28) & 63;
        int tap = i / (28*64);
        g_omwT[i] = (j < 27) ? omw[(j*64 + c)*9 + tap] : 0.f;
    }
}

// ---------------------------------------------------------------------------
// Kernel 1: offset/mask conv (64 -> 27ch 3x3), f32x2 packed.
// 2 horizontally adjacent pixels per thread. 256 blocks x 128 threads.
// ---------------------------------------------------------------------------
__global__ void __launch_bounds__(128) k_offsets(const float* __restrict__ om_bias) {
    extern __shared__ float wsm[];      // [tap][c][28]
    int t = threadIdx.x;
    for (int i = t; i < 9*64*28; i += 128) wsm[i] = g_omwT[i];
    __syncthreads();
    unsigned wsm_u = (unsigned)__cvta_generic_to_shared(wsm);

    int lin = blockIdx.x * 128 + t;     // 0..32767 (pixel pairs)
    int w0 = (lin & 63) * 2;
    int h  = (lin >> 6) & 127;
    int b  = lin >> 13;

    u64 acc0[14], acc1[14];             // [j4*2 + half] : j pairs
    #pragma unroll
    for (int j4 = 0; j4 < 7; j4++) {
        float bv[4];
        #pragma unroll
        for (int q = 0; q < 4; q++) {
            int j = j4*4 + q;
            bv[q] = (j < 27) ? __ldg(om_bias + j) : 0.f;
        }
        acc0[j4*2]   = pack2(bv[0], bv[1]);
        acc0[j4*2+1] = pack2(bv[2], bv[3]);
        acc1[j4*2]   = acc0[j4*2];
        acc1[j4*2+1] = acc0[j4*2+1];
    }

    #pragma unroll
    for (int tap = 0; tap < 9; tap++) {
        int ny  = h + tap/3 - 1;
        int nx0 = w0 + tap%3 - 1;
        bool vy = (ny >= 0) && (ny < NH);
        bool v0 = vy && (nx0 >= 0) && (nx0 < NW);
        bool v1 = vy && (nx0 + 1 >= 0) && (nx0 + 1 < NW);
        #pragma unroll
        for (int cg = 0; cg < 16; cg++) {
            float4 p0 = make_float4(0.f,0.f,0.f,0.f);
            float4 p1 = make_float4(0.f,0.f,0.f,0.f);
            if (v0) p0 = *(const float4*)(g_xT + ((((b*16 + cg)*NH + ny)*NW + nx0) << 2));
            if (v1) p1 = *(const float4*)(g_xT + ((((b*16 + cg)*NH + ny)*NW + nx0 + 1) << 2));
            float p0a[4], p1a[4];
            *(float4*)p0a = p0; *(float4*)p1a = p1;
            #pragma unroll
            for (int ci = 0; ci < 4; ci++) {
                u64 a0d = dup2(p0a[ci]);
                u64 a1d = dup2(p1a[ci]);
                unsigned wa = wsm_u + ((tap*64 + cg*4 + ci)*28) * 4;
                #pragma unroll
                for (int j4 = 0; j4 < 7; j4++) {
                    u64 wlo, whi;
                    lds128_2(wa + j4*16, wlo, whi);
                    acc0[j4*2]   = ffma2(wlo, a0d, acc0[j4*2]);
                    acc0[j4*2+1] = ffma2(whi, a0d, acc0[j4*2+1]);
                    acc1[j4*2]   = ffma2(wlo, a1d, acc1[j4*2]);
                    acc1[j4*2+1] = ffma2(whi, a1d, acc1[j4*2+1]);
                }
            }
        }
    }

    float o0[28], o1[28];
    #pragma unroll
    for (int j4 = 0; j4 < 7; j4++) {
        unpack2(acc0[j4*2],   o0[j4*4],   o0[j4*4+1]);
        unpack2(acc0[j4*2+1], o0[j4*4+2], o0[j4*4+3]);
        unpack2(acc1[j4*2],   o1[j4*4],   o1[j4*4+1]);
        unpack2(acc1[j4*2+1], o1[j4*4+2], o1[j4*4+3]);
    }

    #pragma unroll
    for (int k = 0; k < 9; k++) {
        int off = ((b*9 + k)*NH + h)*NW + w0;
        float ky = (float)(k/3), kx = (float)(k%3);
        g_py[off]     = o0[2*k]   + ky + (float)(h - 1);
        g_py[off + 1] = o1[2*k]   + ky + (float)(h - 1);
        g_px[off]     = o0[2*k+1] + kx + (float)(w0 - 1);
        g_px[off + 1] = o1[2*k+1] + kx + (float)(w0);
        g_ms[off]     = 1.f / (1.f + expf(-o0[18+k]));
        g_ms[off + 1] = 1.f / (1.f + expf(-o1[18+k]));
    }
}

// ---------------------------------------------------------------------------
// Gather one tap's 64c x 64px tile into smem buf (bilinear blend, f32x2).
// ---------------------------------------------------------------------------
__device__ __forceinline__ void gather_tap(const char* __restrict__ xb,
                                           int mi, int px, int cg0,
                                           float* __restrict__ buf) {
    float py  = __ldg(g_py + mi);
    float pxx = __ldg(g_px + mi);
    float m   = __ldg(g_ms + mi);
    float y0f = floorf(py), x0f = floorf(pxx);
    float wy = py - y0f, wx = pxx - x0f;
    bool vy0 = (y0f >=  0.f) && (y0f <= 127.f);
    bool vy1 = (y0f >= -1.f) && (y0f <= 126.f);
    bool vx0 = (x0f >=  0.f) && (x0f <= 127.f);
    bool vx1 = (x0f >= -1.f) && (x0f <= 126.f);
    int iy0 = (int)fminf(fmaxf(y0f,       0.f), 127.f);
    int iy1 = (int)fminf(fmaxf(y0f + 1.f, 0.f), 127.f);
    int ix0 = (int)fminf(fmaxf(x0f,       0.f), 127.f);
    int ix1 = (int)fminf(fmaxf(x0f + 1.f, 0.f), 127.f);
    u64 w00d = dup2((1.f-wy)*(1.f-wx) * ((vy0 && vx0) ? m : 0.f));
    u64 w01d = dup2((1.f-wy)*wx       * ((vy0 && vx1) ? m : 0.f));
    u64 w10d = dup2(wy*(1.f-wx)       * ((vy1 && vx0) ? m : 0.f));
    u64 w11d = dup2(wy*wx             * ((vy1 && vx1) ? m : 0.f));
    int i00 = iy0*NW + ix0, i01 = iy0*NW + ix1;
    int i10 = iy1*NW + ix0, i11 = iy1*NW + ix1;
    #pragma unroll
    for (int it = 0; it < 4; it++) {
        int cg = it*4 + cg0;
        const char* cb = xb + ((size_t)cg*HW << 4);
        u64 Alo, Ahi, Blo, Bhi, Clo, Chi, Dlo, Dhi;
        ldg128_2(cb + ((size_t)i00 << 4), Alo, Ahi);
        ldg128_2(cb + ((size_t)i01 << 4), Blo, Bhi);
        ldg128_2(cb + ((size_t)i10 << 4), Clo, Chi);
        ldg128_2(cb + ((size_t)i11 << 4), Dlo, Dhi);
        u64 vlo = ffma2(w00d, Alo, ffma2(w01d, Blo, ffma2(w10d, Clo, fmul2(w11d, Dlo))));
        u64 vhi = ffma2(w00d, Ahi, ffma2(w01d, Bhi, ffma2(w10d, Chi, fmul2(w11d, Dhi))));
        float sx, sy, sz, sw;
        unpack2(vlo, sx, sy);
        unpack2(vhi, sz, sw);
        int sb = (cg*4)*64 + px;
        buf[sb]       = sx;
        buf[sb +  64] = sy;
        buf[sb + 128] = sz;
        buf[sb + 192] = sw;
    }
}

// ---------------------------------------------------------------------------
// Kernel 2: bilinear sampling + output GEMM (f32x2), pipelined over taps.
// One block per (b,h,half-row): 1024 blocks x 256 threads.
// samp[64c][64px] double-buffered (2 x 16KB smem), one barrier per tap.
// GEMM register tile: 4o x 4px per thread, accumulators are px-pairs.
// ---------------------------------------------------------------------------
__global__ void __launch_bounds__(256) k_main(const float* __restrict__ bias,
                                              float* __restrict__ out) {
    extern __shared__ float ssamp[];    // [2][64*64]
    unsigned smem_u = (unsigned)__cvta_generic_to_shared(ssamp);
    int t = threadIdx.x;
    int blk = blockIdx.x;
    int half = blk & 1;
    int h = (blk >> 1) & 127;
    int b = blk >> 8;
    int w0 = half * 64;

    int px  = t & 63;                   // gather: pixel owned (local)
    int cg0 = t >> 6;                   // 0..3
    int o_base  = (t >> 4) * 4;         // GEMM: 4 outputs
    int px_base = (t & 15) * 4;         // GEMM: 4 pixels (local)

    const char* xb = (const char*)g_xT + (((size_t)(b*16))*HW << 4);
    int offm = (b*9)*HW + h*NW + w0 + px;

    u64 acc01[4], acc23[4];             // [oi]: px pairs (0,1) and (2,3)
    u64 z = dup2(0.f);
    #pragma unroll
    for (int i = 0; i < 4; i++) { acc01[i] = z; acc23[i] = z; }

    // prologue: gather tap 0 into buf 0
    gather_tap(xb, offm, px, cg0, ssamp);
    __syncthreads();

    for (int k = 0; k < 9; k++) {
        unsigned sbase = smem_u + ((k & 1) * 4096 + px_base) * 4;
        const float* wk = g_Wt + k*4096 + o_base;
        #pragma unroll 8
        for (int c = 0; c < 64; c++) {
            u64 wp01, wp23;
            ldg128_2(wk + c*64, wp01, wp23);
            float wx_, wy_, wz_, ww_;
            unpack2(wp01, wx_, wy_);
            unpack2(wp23, wz_, ww_);
            u64 s01, s23;
            lds128_2(sbase + c*256, s01, s23);
            u64 w0d = dup2(wx_), w1d = dup2(wy_), w2d = dup2(wz_), w3d = dup2(ww_);
            acc01[0] = ffma2(w0d, s01, acc01[0]); acc23[0] = ffma2(w0d, s23, acc23[0]);
            acc01[1] = ffma2(w1d, s01, acc01[1]); acc23[1] = ffma2(w1d, s23, acc23[1]);
            acc01[2] = ffma2(w2d, s01, acc01[2]); acc23[2] = ffma2(w2d, s23, acc23[2]);
            acc01[3] = ffma2(w3d, s01, acc01[3]); acc23[3] = ffma2(w3d, s23, acc23[3]);
        }
        if (k < 8)
            gather_tap(xb, offm + (k+1)*HW, px, cg0, ssamp + ((k+1) & 1) * 4096);
        __syncthreads();
    }

    #pragma unroll
    for (int oi = 0; oi < 4; oi++) {
        float bv = __ldg(bias + o_base + oi);
        float4 r;
        unpack2(acc01[oi], r.x, r.y);
        unpack2(acc23[oi], r.z, r.w);
        r.x += bv; r.y += bv; r.z += bv; r.w += bv;
        *(float4*)(out + (((b*64 + o_base + oi)*NH + h)*NW) + w0 + px_base) = r;
    }
}

// ---------------------------------------------------------------------------
extern "C" void kernel_launch(void* const* d_in, const int* in_sizes, int n_in,
                              void* d_out, int out_size) {
    const float* x         = (const float*)d_in[0];
    const float* weight    = (const float*)d_in[1];
    const float* bias      = (const float*)d_in[2];
    const float* om_weight = (const float*)d_in[3];
    const float* om_bias   = (const float*)d_in[4];
    float* out = (float*)d_out;

    cudaFuncSetAttribute(k_offsets, cudaFuncAttributeMaxDynamicSharedMemorySize, 9*64*28*4);

    k_transpose<<<2048, 256>>>(x);
    k_reorg<<<144, 256>>>(weight, om_weight);
    k_offsets<<<256, 128, 9*64*28*4>>>(om_bias);
    k_main<<<1024, 256, 2*64*64*4>>>(bias, out);
}

// round 7
// speedup vs baseline: 1.0269x; 1.0269x over previous
#include <cuda_runtime.h>
#include <math.h>
#include <stdint.h>

#define NB 4
#define NC 64
#define NO 64
#define NH 128
#define NW 128
#define HW (NH*NW)

typedef unsigned long long u64;

// ---- f32x2 packed helpers (sm_100+) ---------------------------------------
__device__ __forceinline__ u64 dup2(float v) {
    u64 r; asm("mov.b64 %0, {%1, %1};" : "=l"(r) : "f"(v)); return r;
}
__device__ __forceinline__ void unpack2(u64 p, float& lo, float& hi) {
    asm("mov.b64 {%0, %1}, %2;" : "=f"(lo), "=f"(hi) : "l"(p));
}
__device__ __forceinline__ u64 ffma2(u64 a, u64 b, u64 c) {
    u64 d; asm("fma.rn.f32x2 %0, %1, %2, %3;" : "=l"(d) : "l"(a), "l"(b), "l"(c)); return d;
}
__device__ __forceinline__ u64 fmul2(u64 a, u64 b) {
    u64 d; asm("mul.rn.f32x2 %0, %1, %2;" : "=l"(d) : "l"(a), "l"(b)); return d;
}
__device__ __forceinline__ void ldg128_2(const void* p, u64& lo, u64& hi) {
    asm("ld.global.nc.v2.u64 {%0,%1}, [%2];" : "=l"(lo), "=l"(hi) : "l"(p));
}
__device__ __forceinline__ void lds128_2(unsigned addr, u64& lo, u64& hi) {
    asm("ld.shared.v2.u64 {%0,%1}, [%2];" : "=l"(lo), "=l"(hi) : "r"(addr));
}

// Scratch (static device globals — no allocation)
__device__ float g_xT[NB*16*HW*4];      // x repacked: [b][c/4][h][w][4]
__device__ float g_py[NB*9*HW];         // sample y coord per (b,k,h,w)
__device__ float g_px[NB*9*HW];         // sample x coord
__device__ float g_ms[NB*9*HW];         // sigmoid(mask)
__device__ float g_Wt[9*64*64];         // weight repacked: [k][c][o]
__device__ float g_omwT[9*64*28];       // om_weight repacked: [tap][c][j(pad28)]

// ---------------------------------------------------------------------------
// Kernel 0: NCHW -> [b][c/4][h][w][4] repack (coalesced via smem tile)
// ---------------------------------------------------------------------------
__global__ void __launch_bounds__(256) k_transpose(const float* __restrict__ x) {
    __shared__ float ts[64][33];
    int blk = blockIdx.x;
    int wc = blk & 3;
    int h  = (blk >> 2) & 127;
    int b  = blk >> 9;
    int w0 = wc * 32;
    int t = threadIdx.x;
    #pragma unroll
    for (int i = 0; i < 8; i++) {
        int idx = i * 256 + t;
        int c = idx >> 5, w = idx & 31;
        ts[c][w] = x[((b*64 + c)*NH + h)*NW + w0 + w];
    }
    __syncthreads();
    #pragma unroll
    for (int i = 0; i < 8; i++) {
        int idx = i * 256 + t;
        int comp = idx & 3, w = (idx >> 2) & 31, cg = idx >> 7;
        g_xT[((((b*16 + cg)*NH + h)*NW + w0 + w) << 2) + comp] = ts[cg*4 + comp][w];
    }
}

// ---------------------------------------------------------------------------
// Kernel R: weight reorganizations.
// ---------------------------------------------------------------------------
__global__ void __launch_bounds__(256) k_reorg(const float* __restrict__ wgt,
                                               const float* __restrict__ omw) {
    int i = blockIdx.x * 256 + threadIdx.x;
    if (i < 9*64*64) {              // g_Wt[k][c][o] = weight[o][c][k]
        int o = i & 63, c = (i >> 6) & 63, k = i >> 12;
        g_Wt[i] = wgt[(o*64 + c)*9 + k];
    }
    if (i < 9*64*28) {              // g_omwT[tap][c][j] = om_weight[j][c][tap]
        int j = i % 28;
        int c = (i / 28) & 63;
        int tap = i / (28*64);
        g_omwT[i] = (j < 27) ? omw[(j*64 + c)*9 + tap] : 0.f;
    }
}

// ---------------------------------------------------------------------------
// Kernel 1: offset/mask conv (64 -> 27ch 3x3). R1-proven version.
// 2 horizontally adjacent pixels per thread. 128 blocks x 256 threads.
// ---------------------------------------------------------------------------
__global__ void __launch_bounds__(256) k_offsets(const float* __restrict__ om_bias) {
    extern __shared__ float wsm[];      // [tap][c][28]
    int t = threadIdx.x;
    for (int i = t; i < 9*64*28; i += 256) wsm[i] = g_omwT[i];
    __syncthreads();

    int lin = blockIdx.x * 256 + t;     // 0..32767 (pixel pairs)
    int w0 = (lin & 63) * 2;
    int h  = (lin >> 6) & 127;
    int b  = lin >> 13;

    float4 acc0[7], acc1[7];
    #pragma unroll
    for (int j4 = 0; j4 < 7; j4++) {
        float bv[4];
        #pragma unroll
        for (int q = 0; q < 4; q++) {
            int j = j4*4 + q;
            bv[q] = (j < 27) ? __ldg(om_bias + j) : 0.f;
        }
        acc0[j4] = make_float4(bv[0], bv[1], bv[2], bv[3]);
        acc1[j4] = acc0[j4];
    }

    #pragma unroll
    for (int tap = 0; tap < 9; tap++) {
        int ny  = h + tap/3 - 1;
        int nx0 = w0 + tap%3 - 1;
        bool vy = (ny >= 0) && (ny < NH);
        bool v0 = vy && (nx0 >= 0) && (nx0 < NW);
        bool v1 = vy && (nx0 + 1 >= 0) && (nx0 + 1 < NW);
        #pragma unroll
        for (int cg = 0; cg < 16; cg++) {
            float4 p0 = make_float4(0.f,0.f,0.f,0.f);
            float4 p1 = make_float4(0.f,0.f,0.f,0.f);
            if (v0) p0 = *(const float4*)(g_xT + ((((b*16 + cg)*NH + ny)*NW + nx0) << 2));
            if (v1) p1 = *(const float4*)(g_xT + ((((b*16 + cg)*NH + ny)*NW + nx0 + 1) << 2));
            float p0a[4], p1a[4];
            *(float4*)p0a = p0; *(float4*)p1a = p1;
            const float* wr = &wsm[(tap*64 + cg*4)*28];
            #pragma unroll
            for (int ci = 0; ci < 4; ci++) {
                float a0 = p0a[ci], a1 = p1a[ci];
                #pragma unroll
                for (int j4 = 0; j4 < 7; j4++) {
                    float4 w4 = *(const float4*)(wr + ci*28 + j4*4);
                    acc0[j4].x += a0*w4.x; acc0[j4].y += a0*w4.y;
                    acc0[j4].z += a0*w4.z; acc0[j4].w += a0*w4.w;
                    acc1[j4].x += a1*w4.x; acc1[j4].y += a1*w4.y;
                    acc1[j4].z += a1*w4.z; acc1[j4].w += a1*w4.w;
                }
            }
        }
    }

    float o0[28], o1[28];
    #pragma unroll
    for (int j4 = 0; j4 < 7; j4++) {
        ((float4*)o0)[j4] = acc0[j4];
        ((float4*)o1)[j4] = acc1[j4];
    }

    #pragma unroll
    for (int k = 0; k < 9; k++) {
        int off = ((b*9 + k)*NH + h)*NW + w0;
        float ky = (float)(k/3), kx = (float)(k%3);
        g_py[off]     = o0[2*k]   + ky + (float)(h - 1);
        g_py[off + 1] = o1[2*k]   + ky + (float)(h - 1);
        g_px[off]     = o0[2*k+1] + kx + (float)(w0 - 1);
        g_px[off + 1] = o1[2*k+1] + kx + (float)(w0);
        g_ms[off]     = 1.f / (1.f + expf(-o0[18+k]));
        g_ms[off + 1] = 1.f / (1.f + expf(-o1[18+k]));
    }
}

// ---------------------------------------------------------------------------
// Gather one tap's 64c x 64px tile into smem buf (bilinear blend, f32x2).
// 128 threads: px = t&63, cgh = t>>6 (0/1); 8 cg iters (cg = it*2 + cgh).
// ---------------------------------------------------------------------------
__device__ __forceinline__ void gather_tap(const char* __restrict__ xb,
                                           int mi, int px, int cgh,
                                           float* __restrict__ buf) {
    float py  = __ldg(g_py + mi);
    float pxx = __ldg(g_px + mi);
    float m   = __ldg(g_ms + mi);
    float y0f = floorf(py), x0f = floorf(pxx);
    float wy = py - y0f, wx = pxx - x0f;
    bool vy0 = (y0f >=  0.f) && (y0f <= 127.f);
    bool vy1 = (y0f >= -1.f) && (y0f <= 126.f);
    bool vx0 = (x0f >=  0.f) && (x0f <= 127.f);
    bool vx1 = (x0f >= -1.f) && (x0f <= 126.f);
    int iy0 = (int)fminf(fmaxf(y0f,       0.f), 127.f);
    int iy1 = (int)fminf(fmaxf(y0f + 1.f, 0.f), 127.f);
    int ix0 = (int)fminf(fmaxf(x0f,       0.f), 127.f);
    int ix1 = (int)fminf(fmaxf(x0f + 1.f, 0.f), 127.f);
    u64 w00d = dup2((1.f-wy)*(1.f-wx) * ((vy0 && vx0) ? m : 0.f));
    u64 w01d = dup2((1.f-wy)*wx       * ((vy0 && vx1) ? m : 0.f));
    u64 w10d = dup2(wy*(1.f-wx)       * ((vy1 && vx0) ? m : 0.f));
    u64 w11d = dup2(wy*wx             * ((vy1 && vx1) ? m : 0.f));
    int i00 = iy0*NW + ix0, i01 = iy0*NW + ix1;
    int i10 = iy1*NW + ix0, i11 = iy1*NW + ix1;
    #pragma unroll
    for (int it = 0; it < 8; it++) {
        int cg = it*2 + cgh;                 // 0..15
        const char* cb = xb + ((size_t)cg*HW << 4);
        u64 Alo, Ahi, Blo, Bhi, Clo, Chi, Dlo, Dhi;
        ldg128_2(cb + ((size_t)i00 << 4), Alo, Ahi);
        ldg128_2(cb + ((size_t)i01 << 4), Blo, Bhi);
        ldg128_2(cb + ((size_t)i10 << 4), Clo, Chi);
        ldg128_2(cb + ((size_t)i11 << 4), Dlo, Dhi);
        u64 vlo = ffma2(w00d, Alo, ffma2(w01d, Blo, ffma2(w10d, Clo, fmul2(w11d, Dlo))));
        u64 vhi = ffma2(w00d, Ahi, ffma2(w01d, Bhi, ffma2(w10d, Chi, fmul2(w11d, Dhi))));
        float s0, s1, s2, s3;
        unpack2(vlo, s0, s1);
        unpack2(vhi, s2, s3);
        int sb = (cg*4)*64 + px;
        buf[sb]       = s0;
        buf[sb +  64] = s1;
        buf[sb + 128] = s2;
        buf[sb + 192] = s3;
    }
}

// ---------------------------------------------------------------------------
// Kernel 2: bilinear sampling + output GEMM, pipelined over taps.
// 128-thread CTAs, one per (b,h,half): 1024 blocks. 32KB static smem,
// ~6 CTAs/SM. Warp tile 32px x 32o; thread tile 4px x 8o.
// Per c per warp: 1 broadcast LDS wavefront (S) + 2 semi-uniform LDGs (W).
// ---------------------------------------------------------------------------
__global__ void __launch_bounds__(128, 6) k_main(const float* __restrict__ bias,
                                                 float* __restrict__ out) {
    __shared__ float ssamp[2][64*64];   // 32 KB
    unsigned smem_u = (unsigned)__cvta_generic_to_shared(ssamp);
    int t = threadIdx.x;
    int blk = blockIdx.x;
    int half = blk & 1;
    int h = (blk >> 1) & 127;
    int b = blk >> 8;
    int w0 = half * 64;

    int px  = t & 63;                   // gather: pixel owned (local)
    int cgh = t >> 6;                   // 0 or 1
    int wid = t >> 5, lid = t & 31;
    int px_base = (wid & 1)*32 + (lid & 7)*4;    // GEMM: 4 pixels
    int o_base  = (wid >> 1)*32 + (lid >> 3)*8;  // GEMM: 8 outputs

    const char* xb = (const char*)g_xT + (((size_t)(b*16))*HW << 4);
    int offm = (b*9)*HW + h*NW + w0 + px;

    u64 acc01[8], acc23[8];             // [oi]: px pairs (0,1) and (2,3)
    u64 z = dup2(0.f);
    #pragma unroll
    for (int i = 0; i < 8; i++) { acc01[i] = z; acc23[i] = z; }

    // prologue: gather tap 0 into buf 0
    gather_tap(xb, offm, px, cgh, ssamp[0]);
    __syncthreads();

    for (int k = 0; k < 9; k++) {
        unsigned sbase = smem_u + ((k & 1) * 4096 + px_base) * 4;
        const float* wk = g_Wt + k*4096 + o_base;
        #pragma unroll 8
        for (int c = 0; c < 64; c++) {
            u64 s01, s23;
            lds128_2(sbase + c*256, s01, s23);
            u64 wpa, wpb, wpc, wpd;
            ldg128_2(wk + c*64,     wpa, wpb);
            ldg128_2(wk + c*64 + 4, wpc, wpd);
            float w_[8];
            unpack2(wpa, w_[0], w_[1]);
            unpack2(wpb, w_[2], w_[3]);
            unpack2(wpc, w_[4], w_[5]);
            unpack2(wpd, w_[6], w_[7]);
            #pragma unroll
            for (int oi = 0; oi < 8; oi++) {
                u64 wd = dup2(w_[oi]);
                acc01[oi] = ffma2(wd, s01, acc01[oi]);
                acc23[oi] = ffma2(wd, s23, acc23[oi]);
            }
        }
        if (k < 8)
            gather_tap(xb, offm + (k+1)*HW, px, cgh, ssamp[(k+1) & 1]);
        __syncthreads();
    }

    #pragma unroll
    for (int oi = 0; oi < 8; oi++) {
        float bv = __ldg(bias + o_base + oi);
        float4 r;
        unpack2(acc01[oi], r.x, r.y);
        unpack2(acc23[oi], r.z, r.w);
        r.x += bv; r.y += bv; r.z += bv; r.w += bv;
        *(float4*)(out + (((b*64 + o_base + oi)*NH + h)*NW) + w0 + px_base) = r;
    }
}

// ---------------------------------------------------------------------------
extern "C" void kernel_launch(void* const* d_in, const int* in_sizes, int n_in,
                              void* d_out, int out_size) {
    const float* x         = (const float*)d_in[0];
    const float* weight    = (const float*)d_in[1];
    const float* bias      = (const float*)d_in[2];
    const float* om_weight = (const float*)d_in[3];
    const float* om_bias   = (const float*)d_in[4];
    float* out = (float*)d_out;

    cudaFuncSetAttribute(k_offsets, cudaFuncAttributeMaxDynamicSharedMemorySize, 9*64*28*4);

    k_transpose<<<2048, 256>>>(x);
    k_reorg<<<144, 256>>>(weight, om_weight);
    k_offsets<<<128, 256, 9*64*28*4>>>(om_bias);
    k_main<<<1024, 128>>>(bias, out);
}

// round 8
// speedup vs baseline: 1.1284x; 1.0989x over previous
#include <cuda_runtime.h>
#include <math.h>
#include <stdint.h>

#define NB 4
#define NC 64
#define NO 64
#define NH 128
#define NW 128
#define HW (NH*NW)

typedef unsigned long long u64;

// ---- f32x2 packed helpers (sm_100+) ---------------------------------------
__device__ __forceinline__ u64 dup2(float v) {
    u64 r; asm("mov.b64 %0, {%1, %1};" : "=l"(r) : "f"(v)); return r;
}
__device__ __forceinline__ void unpack2(u64 p, float& lo, float& hi) {
    asm("mov.b64 {%0, %1}, %2;" : "=f"(lo), "=f"(hi) : "l"(p));
}
__device__ __forceinline__ u64 ffma2(u64 a, u64 b, u64 c) {
    u64 d; asm("fma.rn.f32x2 %0, %1, %2, %3;" : "=l"(d) : "l"(a), "l"(b), "l"(c)); return d;
}
__device__ __forceinline__ u64 fmul2(u64 a, u64 b) {
    u64 d; asm("mul.rn.f32x2 %0, %1, %2;" : "=l"(d) : "l"(a), "l"(b)); return d;
}
__device__ __forceinline__ void ldg128_2(const void* p, u64& lo, u64& hi) {
    asm("ld.global.nc.v2.u64 {%0,%1}, [%2];" : "=l"(lo), "=l"(hi) : "l"(p));
}
__device__ __forceinline__ void lds128_2(unsigned addr, u64& lo, u64& hi) {
    asm("ld.shared.v2.u64 {%0,%1}, [%2];" : "=l"(lo), "=l"(hi) : "r"(addr));
}

// Scratch (static device globals — no allocation)
__device__ float g_xT[NB*16*HW*4];      // x repacked: [b][c/4][h][w][4]
__device__ float g_py[NB*9*HW];         // sample y coord per (b,k,h,w)
__device__ float g_px[NB*9*HW];         // sample x coord
__device__ float g_ms[NB*9*HW];         // sigmoid(mask)
__device__ float g_Wt[9*64*64];         // weight repacked: [k][c][o]
__device__ float g_omwT[9*64*28];       // om_weight repacked: [tap][c][j(pad28)]

// ---------------------------------------------------------------------------
// Kernel 0: NCHW -> [b][c/4][h][w][4] repack (coalesced via smem tile)
// ---------------------------------------------------------------------------
__global__ void __launch_bounds__(256) k_transpose(const float* __restrict__ x) {
    __shared__ float ts[64][33];
    int blk = blockIdx.x;
    int wc = blk & 3;
    int h  = (blk >> 2) & 127;
    int b  = blk >> 9;
    int w0 = wc * 32;
    int t = threadIdx.x;
    #pragma unroll
    for (int i = 0; i < 8; i++) {
        int idx = i * 256 + t;
        int c = idx >> 5, w = idx & 31;
        ts[c][w] = x[((b*64 + c)*NH + h)*NW + w0 + w];
    }
    __syncthreads();
    #pragma unroll
    for (int i = 0; i < 8; i++) {
        int idx = i * 256 + t;
        int comp = idx & 3, w = (idx >> 2) & 31, cg = idx >> 7;
        g_xT[((((b*16 + cg)*NH + h)*NW + w0 + w) << 2) + comp] = ts[cg*4 + comp][w];
    }
}

// ---------------------------------------------------------------------------
// Kernel R: weight reorganizations.
// ---------------------------------------------------------------------------
__global__ void __launch_bounds__(256) k_reorg(const float* __restrict__ wgt,
                                               const float* __restrict__ omw) {
    int i = blockIdx.x * 256 + threadIdx.x;
    if (i < 9*64*64) {              // g_Wt[k][c][o] = weight[o][c][k]
        int o = i & 63, c = (i >> 6) & 63, k = i >> 12;
        g_Wt[i] = wgt[(o*64 + c)*9 + k];
    }
    if (i < 9*64*28) {              // g_omwT[tap][c][j] = om_weight[j][c][tap]
        int j = i % 28;
        int c = (i / 28) & 63;
        int tap = i / (28*64);
        g_omwT[i] = (j < 27) ? omw[(j*64 + c)*9 + tap] : 0.f;
    }
}

// ---------------------------------------------------------------------------
// Kernel 1: offset/mask conv (64 -> 27ch 3x3). R1-proven version.
// 2 horizontally adjacent pixels per thread. 128 blocks x 256 threads.
// ---------------------------------------------------------------------------
__global__ void __launch_bounds__(256) k_offsets(const float* __restrict__ om_bias) {
    extern __shared__ float wsm[];      // [tap][c][28]
    int t = threadIdx.x;
    for (int i = t; i < 9*64*28; i += 256) wsm[i] = g_omwT[i];
    __syncthreads();

    int lin = blockIdx.x * 256 + t;     // 0..32767 (pixel pairs)
    int w0 = (lin & 63) * 2;
    int h  = (lin >> 6) & 127;
    int b  = lin >> 13;

    float4 acc0[7], acc1[7];
    #pragma unroll
    for (int j4 = 0; j4 < 7; j4++) {
        float bv[4];
        #pragma unroll
        for (int q = 0; q < 4; q++) {
            int j = j4*4 + q;
            bv[q] = (j < 27) ? __ldg(om_bias + j) : 0.f;
        }
        acc0[j4] = make_float4(bv[0], bv[1], bv[2], bv[3]);
        acc1[j4] = acc0[j4];
    }

    #pragma unroll
    for (int tap = 0; tap < 9; tap++) {
        int ny  = h + tap/3 - 1;
        int nx0 = w0 + tap%3 - 1;
        bool vy = (ny >= 0) && (ny < NH);
        bool v0 = vy && (nx0 >= 0) && (nx0 < NW);
        bool v1 = vy && (nx0 + 1 >= 0) && (nx0 + 1 < NW);
        #pragma unroll
        for (int cg = 0; cg < 16; cg++) {
            float4 p0 = make_float4(0.f,0.f,0.f,0.f);
            float4 p1 = make_float4(0.f,0.f,0.f,0.f);
            if (v0) p0 = *(const float4*)(g_xT + ((((b*16 + cg)*NH + ny)*NW + nx0) << 2));
            if (v1) p1 = *(const float4*)(g_xT + ((((b*16 + cg)*NH + ny)*NW + nx0 + 1) << 2));
            float p0a[4], p1a[4];
            *(float4*)p0a = p0; *(float4*)p1a = p1;
            const float* wr = &wsm[(tap*64 + cg*4)*28];
            #pragma unroll
            for (int ci = 0; ci < 4; ci++) {
                float a0 = p0a[ci], a1 = p1a[ci];
                #pragma unroll
                for (int j4 = 0; j4 < 7; j4++) {
                    float4 w4 = *(const float4*)(wr + ci*28 + j4*4);
                    acc0[j4].x += a0*w4.x; acc0[j4].y += a0*w4.y;
                    acc0[j4].z += a0*w4.z; acc0[j4].w += a0*w4.w;
                    acc1[j4].x += a1*w4.x; acc1[j4].y += a1*w4.y;
                    acc1[j4].z += a1*w4.z; acc1[j4].w += a1*w4.w;
                }
            }
        }
    }

    float o0[28], o1[28];
    #pragma unroll
    for (int j4 = 0; j4 < 7; j4++) {
        ((float4*)o0)[j4] = acc0[j4];
        ((float4*)o1)[j4] = acc1[j4];
    }

    #pragma unroll
    for (int k = 0; k < 9; k++) {
        int off = ((b*9 + k)*NH + h)*NW + w0;
        float ky = (float)(k/3), kx = (float)(k%3);
        g_py[off]     = o0[2*k]   + ky + (float)(h - 1);
        g_py[off + 1] = o1[2*k]   + ky + (float)(h - 1);
        g_px[off]     = o0[2*k+1] + kx + (float)(w0 - 1);
        g_px[off + 1] = o1[2*k+1] + kx + (float)(w0);
        g_ms[off]     = 1.f / (1.f + expf(-o0[18+k]));
        g_ms[off + 1] = 1.f / (1.f + expf(-o1[18+k]));
    }
}

// ---------------------------------------------------------------------------
// Gather one tap's 64c x 64px tile into smem buf (bilinear blend, f32x2).
// 64 threads: each owns ONE pixel, loops all 16 channel groups.
// ---------------------------------------------------------------------------
__device__ __forceinline__ void gather_tap(const char* __restrict__ xb,
                                           int mi, int px,
                                           float* __restrict__ buf) {
    float py  = __ldg(g_py + mi);
    float pxx = __ldg(g_px + mi);
    float m   = __ldg(g_ms + mi);
    float y0f = floorf(py), x0f = floorf(pxx);
    float wy = py - y0f, wx = pxx - x0f;
    bool vy0 = (y0f >=  0.f) && (y0f <= 127.f);
    bool vy1 = (y0f >= -1.f) && (y0f <= 126.f);
    bool vx0 = (x0f >=  0.f) && (x0f <= 127.f);
    bool vx1 = (x0f >= -1.f) && (x0f <= 126.f);
    int iy0 = (int)fminf(fmaxf(y0f,       0.f), 127.f);
    int iy1 = (int)fminf(fmaxf(y0f + 1.f, 0.f), 127.f);
    int ix0 = (int)fminf(fmaxf(x0f,       0.f), 127.f);
    int ix1 = (int)fminf(fmaxf(x0f + 1.f, 0.f), 127.f);
    u64 w00d = dup2((1.f-wy)*(1.f-wx) * ((vy0 && vx0) ? m : 0.f));
    u64 w01d = dup2((1.f-wy)*wx       * ((vy0 && vx1) ? m : 0.f));
    u64 w10d = dup2(wy*(1.f-wx)       * ((vy1 && vx0) ? m : 0.f));
    u64 w11d = dup2(wy*wx             * ((vy1 && vx1) ? m : 0.f));
    int i00 = iy0*NW + ix0, i01 = iy0*NW + ix1;
    int i10 = iy1*NW + ix0, i11 = iy1*NW + ix1;
    #pragma unroll 4
    for (int cg = 0; cg < 16; cg++) {
        const char* cb = xb + ((size_t)cg*HW << 4);
        u64 Alo, Ahi, Blo, Bhi, Clo, Chi, Dlo, Dhi;
        ldg128_2(cb + ((size_t)i00 << 4), Alo, Ahi);
        ldg128_2(cb + ((size_t)i01 << 4), Blo, Bhi);
        ldg128_2(cb + ((size_t)i10 << 4), Clo, Chi);
        ldg128_2(cb + ((size_t)i11 << 4), Dlo, Dhi);
        u64 vlo = ffma2(w00d, Alo, ffma2(w01d, Blo, ffma2(w10d, Clo, fmul2(w11d, Dlo))));
        u64 vhi = ffma2(w00d, Ahi, ffma2(w01d, Bhi, ffma2(w10d, Chi, fmul2(w11d, Dhi))));
        float s0, s1, s2, s3;
        unpack2(vlo, s0, s1);
        unpack2(vhi, s2, s3);
        int sb = (cg*4)*64 + px;
        buf[sb]       = s0;
        buf[sb +  64] = s1;
        buf[sb + 128] = s2;
        buf[sb + 192] = s3;
    }
}

// ---------------------------------------------------------------------------
// Kernel 2: bilinear sampling + output GEMM, pipelined over taps.
// 64-thread CTAs, one per (b,h,half): 1024 blocks, 32KB smem, 6 CTAs/SM
// -> ~1 wave. Thread tile 8px x 8o (64 threads cover 64px x 64o).
// Per c-iter: 2 LDS.128 + 2 LDG.128 + 32 ffma2. One barrier per tap (2 warps).
// ---------------------------------------------------------------------------
__global__ void __launch_bounds__(64, 6) k_main(const float* __restrict__ bias,
                                                float* __restrict__ out) {
    __shared__ float ssamp[2][64*64];   // 32 KB
    unsigned smem_u = (unsigned)__cvta_generic_to_shared(ssamp);
    int t = threadIdx.x;                // 0..63
    int blk = blockIdx.x;
    int half = blk & 1;
    int h = (blk >> 1) & 127;
    int b = blk >> 8;
    int w0 = half * 64;

    int px = t;                         // gather: one pixel per thread
    int px_base = (t & 7) * 8;          // GEMM: 8 pixels
    int o_base  = (t >> 3) * 8;         // GEMM: 8 outputs

    const char* xb = (const char*)g_xT + (((size_t)(b*16))*HW << 4);
    int offm = (b*9)*HW + h*NW + w0 + px;

    // acc[oi][pp]: oi = output, pp = pixel pair (0:px01, 1:px23, 2:px45, 3:px67)
    u64 acc[8][4];
    u64 z = dup2(0.f);
    #pragma unroll
    for (int i = 0; i < 8; i++)
        #pragma unroll
        for (int j = 0; j < 4; j++) acc[i][j] = z;

    // prologue: gather tap 0 into buf 0
    gather_tap(xb, offm, px, ssamp[0]);
    __syncthreads();

    for (int k = 0; k < 9; k++) {
        unsigned sbase = smem_u + ((k & 1) * 4096 + px_base) * 4;
        const float* wk = g_Wt + k*4096 + o_base;
        #pragma unroll 4
        for (int c = 0; c < 64; c++) {
            u64 s01, s23, s45, s67;
            lds128_2(sbase + c*256,      s01, s23);
            lds128_2(sbase + c*256 + 16, s45, s67);
            u64 wpa, wpb, wpc, wpd;
            ldg128_2(wk + c*64,     wpa, wpb);
            ldg128_2(wk + c*64 + 4, wpc, wpd);
            float w_[8];
            unpack2(wpa, w_[0], w_[1]);
            unpack2(wpb, w_[2], w_[3]);
            unpack2(wpc, w_[4], w_[5]);
            unpack2(wpd, w_[6], w_[7]);
            #pragma unroll
            for (int oi = 0; oi < 8; oi++) {
                u64 wd = dup2(w_[oi]);
                acc[oi][0] = ffma2(wd, s01, acc[oi][0]);
                acc[oi][1] = ffma2(wd, s23, acc[oi][1]);
                acc[oi][2] = ffma2(wd, s45, acc[oi][2]);
                acc[oi][3] = ffma2(wd, s67, acc[oi][3]);
            }
        }
        if (k < 8)
            gather_tap(xb, offm + (k+1)*HW, px, ssamp[(k+1) & 1]);
        __syncthreads();
    }

    #pragma unroll
    for (int oi = 0; oi < 8; oi++) {
        float bv = __ldg(bias + o_base + oi);
        float r[8];
        unpack2(acc[oi][0], r[0], r[1]);
        unpack2(acc[oi][1], r[2], r[3]);
        unpack2(acc[oi][2], r[4], r[5]);
        unpack2(acc[oi][3], r[6], r[7]);
        float* ob = out + (((b*64 + o_base + oi)*NH + h)*NW) + w0 + px_base;
        *(float4*)ob       = make_float4(r[0]+bv, r[1]+bv, r[2]+bv, r[3]+bv);
        *(float4*)(ob + 4) = make_float4(r[4]+bv, r[5]+bv, r[6]+bv, r[7]+bv);
    }
}

// ---------------------------------------------------------------------------
extern "C" void kernel_launch(void* const* d_in, const int* in_sizes, int n_in,
                              void* d_out, int out_size) {
    const float* x         = (const float*)d_in[0];
    const float* weight    = (const float*)d_in[1];
    const float* bias      = (const float*)d_in[2];
    const float* om_weight = (const float*)d_in[3];
    const float* om_bias   = (const float*)d_in[4];
    float* out = (float*)d_out;

    cudaFuncSetAttribute(k_offsets, cudaFuncAttributeMaxDynamicSharedMemorySize, 9*64*28*4);

    k_transpose<<<2048, 256>>>(x);
    k_reorg<<<144, 256>>>(weight, om_weight);
    k_offsets<<<128, 256, 9*64*28*4>>>(om_bias);
    k_main<<<1024, 64>>>(bias, out);
}

// round 9
// speedup vs baseline: 1.1697x; 1.0366x over previous
#include <cuda_runtime.h>
#include <math.h>
#include <stdint.h>

#define NB 4
#define NC 64
#define NO 64
#define NH 128
#define NW 128
#define HW (NH*NW)

typedef unsigned long long u64;

// ---- f32x2 packed helpers (sm_100+) ---------------------------------------
__device__ __forceinline__ u64 dup2(float v) {
    u64 r; asm("mov.b64 %0, {%1, %1};" : "=l"(r) : "f"(v)); return r;
}
__device__ __forceinline__ void unpack2(u64 p, float& lo, float& hi) {
    asm("mov.b64 {%0, %1}, %2;" : "=f"(lo), "=f"(hi) : "l"(p));
}
__device__ __forceinline__ u64 ffma2(u64 a, u64 b, u64 c) {
    u64 d; asm("fma.rn.f32x2 %0, %1, %2, %3;" : "=l"(d) : "l"(a), "l"(b), "l"(c)); return d;
}
__device__ __forceinline__ u64 fmul2(u64 a, u64 b) {
    u64 d; asm("mul.rn.f32x2 %0, %1, %2;" : "=l"(d) : "l"(a), "l"(b)); return d;
}
__device__ __forceinline__ void ldg128_2(const void* p, u64& lo, u64& hi) {
    asm("ld.global.nc.v2.u64 {%0,%1}, [%2];" : "=l"(lo), "=l"(hi) : "l"(p));
}
__device__ __forceinline__ void lds128_2(unsigned addr, u64& lo, u64& hi) {
    asm("ld.shared.v2.u64 {%0,%1}, [%2];" : "=l"(lo), "=l"(hi) : "r"(addr));
}

// Scratch (static device globals — no allocation)
__device__ float g_xT[NB*16*HW*4];      // x repacked: [b][c/4][h][w][4]
__device__ float g_py[NB*9*HW];         // sample y coord per (b,k,h,w)
__device__ float g_px[NB*9*HW];         // sample x coord
__device__ float g_ms[NB*9*HW];         // sigmoid(mask)
__device__ float g_Wt[9*64*64];         // weight repacked: [k][c][o]
__device__ float g_omwT[9*64*28];       // om_weight repacked: [tap][c][j(pad28)]

// ---------------------------------------------------------------------------
// Kernel 0: NCHW -> [b][c/4][h][w][4] repack (coalesced via smem tile)
// ---------------------------------------------------------------------------
__global__ void __launch_bounds__(256) k_transpose(const float* __restrict__ x) {
    __shared__ float ts[64][33];
    int blk = blockIdx.x;
    int wc = blk & 3;
    int h  = (blk >> 2) & 127;
    int b  = blk >> 9;
    int w0 = wc * 32;
    int t = threadIdx.x;
    #pragma unroll
    for (int i = 0; i < 8; i++) {
        int idx = i * 256 + t;
        int c = idx >> 5, w = idx & 31;
        ts[c][w] = x[((b*64 + c)*NH + h)*NW + w0 + w];
    }
    __syncthreads();
    #pragma unroll
    for (int i = 0; i < 8; i++) {
        int idx = i * 256 + t;
        int comp = idx & 3, w = (idx >> 2) & 31, cg = idx >> 7;
        g_xT[((((b*16 + cg)*NH + h)*NW + w0 + w) << 2) + comp] = ts[cg*4 + comp][w];
    }
}

// ---------------------------------------------------------------------------
// Kernel R: weight reorganizations.
// ---------------------------------------------------------------------------
__global__ void __launch_bounds__(256) k_reorg(const float* __restrict__ wgt,
                                               const float* __restrict__ omw) {
    int i = blockIdx.x * 256 + threadIdx.x;
    if (i < 9*64*64) {              // g_Wt[k][c][o] = weight[o][c][k]
        int o = i & 63, c = (i >> 6) & 63, k = i >> 12;
        g_Wt[i] = wgt[(o*64 + c)*9 + k];
    }
    if (i < 9*64*28) {              // g_omwT[tap][c][j] = om_weight[j][c][tap]
        int j = i % 28;
        int c = (i / 28) & 63;
        int tap = i / (28*64);
        g_omwT[i] = (j < 27) ? omw[(j*64 + c)*9 + tap] : 0.f;
    }
}

// ---------------------------------------------------------------------------
// Kernel 1: offset/mask conv (64 -> 27ch 3x3). R1-proven version.
// ---------------------------------------------------------------------------
__global__ void __launch_bounds__(256) k_offsets(const float* __restrict__ om_bias) {
    extern __shared__ float wsm[];      // [tap][c][28]
    int t = threadIdx.x;
    for (int i = t; i < 9*64*28; i += 256) wsm[i] = g_omwT[i];
    __syncthreads();

    int lin = blockIdx.x * 256 + t;     // 0..32767 (pixel pairs)
    int w0 = (lin & 63) * 2;
    int h  = (lin >> 6) & 127;
    int b  = lin >> 13;

    float4 acc0[7], acc1[7];
    #pragma unroll
    for (int j4 = 0; j4 < 7; j4++) {
        float bv[4];
        #pragma unroll
        for (int q = 0; q < 4; q++) {
            int j = j4*4 + q;
            bv[q] = (j < 27) ? __ldg(om_bias + j) : 0.f;
        }
        acc0[j4] = make_float4(bv[0], bv[1], bv[2], bv[3]);
        acc1[j4] = acc0[j4];
    }

    #pragma unroll
    for (int tap = 0; tap < 9; tap++) {
        int ny  = h + tap/3 - 1;
        int nx0 = w0 + tap%3 - 1;
        bool vy = (ny >= 0) && (ny < NH);
        bool v0 = vy && (nx0 >= 0) && (nx0 < NW);
        bool v1 = vy && (nx0 + 1 >= 0) && (nx0 + 1 < NW);
        #pragma unroll
        for (int cg = 0; cg < 16; cg++) {
            float4 p0 = make_float4(0.f,0.f,0.f,0.f);
            float4 p1 = make_float4(0.f,0.f,0.f,0.f);
            if (v0) p0 = *(const float4*)(g_xT + ((((b*16 + cg)*NH + ny)*NW + nx0) << 2));
            if (v1) p1 = *(const float4*)(g_xT + ((((b*16 + cg)*NH + ny)*NW + nx0 + 1) << 2));
            float p0a[4], p1a[4];
            *(float4*)p0a = p0; *(float4*)p1a = p1;
            const float* wr = &wsm[(tap*64 + cg*4)*28];
            #pragma unroll
            for (int ci = 0; ci < 4; ci++) {
                float a0 = p0a[ci], a1 = p1a[ci];
                #pragma unroll
                for (int j4 = 0; j4 < 7; j4++) {
                    float4 w4 = *(const float4*)(wr + ci*28 + j4*4);
                    acc0[j4].x += a0*w4.x; acc0[j4].y += a0*w4.y;
                    acc0[j4].z += a0*w4.z; acc0[j4].w += a0*w4.w;
                    acc1[j4].x += a1*w4.x; acc1[j4].y += a1*w4.y;
                    acc1[j4].z += a1*w4.z; acc1[j4].w += a1*w4.w;
                }
            }
        }
    }

    float o0[28], o1[28];
    #pragma unroll
    for (int j4 = 0; j4 < 7; j4++) {
        ((float4*)o0)[j4] = acc0[j4];
        ((float4*)o1)[j4] = acc1[j4];
    }

    #pragma unroll
    for (int k = 0; k < 9; k++) {
        int off = ((b*9 + k)*NH + h)*NW + w0;
        float ky = (float)(k/3), kx = (float)(k%3);
        g_py[off]     = o0[2*k]   + ky + (float)(h - 1);
        g_py[off + 1] = o1[2*k]   + ky + (float)(h - 1);
        g_px[off]     = o0[2*k+1] + kx + (float)(w0 - 1);
        g_px[off + 1] = o1[2*k+1] + kx + (float)(w0);
        g_ms[off]     = 1.f / (1.f + expf(-o0[18+k]));
        g_ms[off + 1] = 1.f / (1.f + expf(-o1[18+k]));
    }
}

// ---------------------------------------------------------------------------
// Meta for one tap (per thread: one pixel).
// ---------------------------------------------------------------------------
struct Meta {
    u64 w00d, w01d, w10d, w11d;
    int i00, i01, i10, i11;
};
__device__ __forceinline__ Meta make_meta(int mi) {
    Meta mt;
    float py  = __ldg(g_py + mi);
    float pxx = __ldg(g_px + mi);
    float m   = __ldg(g_ms + mi);
    float y0f = floorf(py), x0f = floorf(pxx);
    float wy = py - y0f, wx = pxx - x0f;
    bool vy0 = (y0f >=  0.f) && (y0f <= 127.f);
    bool vy1 = (y0f >= -1.f) && (y0f <= 126.f);
    bool vx0 = (x0f >=  0.f) && (x0f <= 127.f);
    bool vx1 = (x0f >= -1.f) && (x0f <= 126.f);
    int iy0 = (int)fminf(fmaxf(y0f,       0.f), 127.f);
    int iy1 = (int)fminf(fmaxf(y0f + 1.f, 0.f), 127.f);
    int ix0 = (int)fminf(fmaxf(x0f,       0.f), 127.f);
    int ix1 = (int)fminf(fmaxf(x0f + 1.f, 0.f), 127.f);
    mt.w00d = dup2((1.f-wy)*(1.f-wx) * ((vy0 && vx0) ? m : 0.f));
    mt.w01d = dup2((1.f-wy)*wx       * ((vy0 && vx1) ? m : 0.f));
    mt.w10d = dup2(wy*(1.f-wx)       * ((vy1 && vx0) ? m : 0.f));
    mt.w11d = dup2(wy*wx             * ((vy1 && vx1) ? m : 0.f));
    mt.i00 = iy0*NW + ix0; mt.i01 = iy0*NW + ix1;
    mt.i10 = iy1*NW + ix0; mt.i11 = iy1*NW + ix1;
    return mt;
}

// Simple full-tap gather (prologue only).
__device__ __forceinline__ void gather_tap(const char* __restrict__ xb,
                                           int mi, int px,
                                           float* __restrict__ buf) {
    Meta mt = make_meta(mi);
    #pragma unroll 4
    for (int cg = 0; cg < 16; cg++) {
        const char* cb = xb + ((size_t)cg*HW << 4);
        u64 Alo, Ahi, Blo, Bhi, Clo, Chi, Dlo, Dhi;
        ldg128_2(cb + ((size_t)mt.i00 << 4), Alo, Ahi);
        ldg128_2(cb + ((size_t)mt.i01 << 4), Blo, Bhi);
        ldg128_2(cb + ((size_t)mt.i10 << 4), Clo, Chi);
        ldg128_2(cb + ((size_t)mt.i11 << 4), Dlo, Dhi);
        u64 vlo = ffma2(mt.w00d, Alo, ffma2(mt.w01d, Blo, ffma2(mt.w10d, Clo, fmul2(mt.w11d, Dlo))));
        u64 vhi = ffma2(mt.w00d, Ahi, ffma2(mt.w01d, Bhi, ffma2(mt.w10d, Chi, fmul2(mt.w11d, Dhi))));
        float s0, s1, s2, s3;
        unpack2(vlo, s0, s1);
        unpack2(vhi, s2, s3);
        int sb = (cg*4)*64 + px;
        buf[sb]       = s0;
        buf[sb +  64] = s1;
        buf[sb + 128] = s2;
        buf[sb + 192] = s3;
    }
}

// ---------------------------------------------------------------------------
// Kernel 2: bilinear sampling + output GEMM, chunk-interleaved pipeline.
// 64-thread CTAs, one per (b,h,half): 1024 blocks, 32KB smem.
// Thread tile 8px x 8o. Per chunk q: issue next-tap corner LDGs for 2 cg,
// run 8 GEMM c-iters (covers load latency), then blend+STS.
// ---------------------------------------------------------------------------
__global__ void __launch_bounds__(64, 5) k_main(const float* __restrict__ bias,
                                                float* __restrict__ out) {
    __shared__ float ssamp[2][64*64];   // 32 KB
    unsigned smem_u = (unsigned)__cvta_generic_to_shared(ssamp);
    int t = threadIdx.x;                // 0..63
    int blk = blockIdx.x;
    int half = blk & 1;
    int h = (blk >> 1) & 127;
    int b = blk >> 8;
    int w0 = half * 64;

    int px = t;                         // gather: one pixel per thread
    int px_base = (t & 7) * 8;          // GEMM: 8 pixels
    int o_base  = (t >> 3) * 8;         // GEMM: 8 outputs

    const char* xb = (const char*)g_xT + (((size_t)(b*16))*HW << 4);
    int offm = (b*9)*HW + h*NW + w0 + px;

    u64 acc[8][4];
    u64 z = dup2(0.f);
    #pragma unroll
    for (int i = 0; i < 8; i++)
        #pragma unroll
        for (int j = 0; j < 4; j++) acc[i][j] = z;

    // prologue: gather tap 0 into buf 0
    gather_tap(xb, offm, px, ssamp[0]);
    __syncthreads();

    #pragma unroll 1
    for (int k = 0; k < 8; k++) {
        unsigned sbase = smem_u + ((k & 1) * 4096 + px_base) * 4;
        const float* wk = g_Wt + k*4096 + o_base;
        float* nbuf = ssamp[(k + 1) & 1];
        Meta mt = make_meta(offm + (k+1)*HW);   // next tap's meta

        #pragma unroll
        for (int q = 0; q < 8; q++) {
            // --- issue next-tap corner loads for cg pair (2q, 2q+1) ---
            const char* cb0 = xb + ((size_t)(2*q)*HW << 4);
            const char* cb1 = xb + ((size_t)(2*q + 1)*HW << 4);
            u64 a0lo, a0hi, b0lo, b0hi, c0lo, c0hi, d0lo, d0hi;
            u64 a1lo, a1hi, b1lo, b1hi, c1lo, c1hi, d1lo, d1hi;
            ldg128_2(cb0 + ((size_t)mt.i00 << 4), a0lo, a0hi);
            ldg128_2(cb0 + ((size_t)mt.i01 << 4), b0lo, b0hi);
            ldg128_2(cb0 + ((size_t)mt.i10 << 4), c0lo, c0hi);
            ldg128_2(cb0 + ((size_t)mt.i11 << 4), d0lo, d0hi);
            ldg128_2(cb1 + ((size_t)mt.i00 << 4), a1lo, a1hi);
            ldg128_2(cb1 + ((size_t)mt.i01 << 4), b1lo, b1hi);
            ldg128_2(cb1 + ((size_t)mt.i10 << 4), c1lo, c1hi);
            ldg128_2(cb1 + ((size_t)mt.i11 << 4), d1lo, d1hi);

            // --- GEMM 8 c-iters on current tap (covers load latency) ---
            #pragma unroll
            for (int ci = 0; ci < 8; ci++) {
                int c = q*8 + ci;
                u64 s01, s23, s45, s67;
                lds128_2(sbase + c*256,      s01, s23);
                lds128_2(sbase + c*256 + 16, s45, s67);
                u64 wpa, wpb, wpc, wpd;
                ldg128_2(wk + c*64,     wpa, wpb);
                ldg128_2(wk + c*64 + 4, wpc, wpd);
                float w_[8];
                unpack2(wpa, w_[0], w_[1]);
                unpack2(wpb, w_[2], w_[3]);
                unpack2(wpc, w_[4], w_[5]);
                unpack2(wpd, w_[6], w_[7]);
                #pragma unroll
                for (int oi = 0; oi < 8; oi++) {
                    u64 wd = dup2(w_[oi]);
                    acc[oi][0] = ffma2(wd, s01, acc[oi][0]);
                    acc[oi][1] = ffma2(wd, s23, acc[oi][1]);
                    acc[oi][2] = ffma2(wd, s45, acc[oi][2]);
                    acc[oi][3] = ffma2(wd, s67, acc[oi][3]);
                }
            }

            // --- blend + store next-tap data (loads have landed) ---
            {
                u64 vlo = ffma2(mt.w00d, a0lo, ffma2(mt.w01d, b0lo, ffma2(mt.w10d, c0lo, fmul2(mt.w11d, d0lo))));
                u64 vhi = ffma2(mt.w00d, a0hi, ffma2(mt.w01d, b0hi, ffma2(mt.w10d, c0hi, fmul2(mt.w11d, d0hi))));
                float s0, s1, s2, s3;
                unpack2(vlo, s0, s1);
                unpack2(vhi, s2, s3);
                int sb = (2*q*4)*64 + px;
                nbuf[sb]       = s0;
                nbuf[sb +  64] = s1;
                nbuf[sb + 128] = s2;
                nbuf[sb + 192] = s3;
                vlo = ffma2(mt.w00d, a1lo, ffma2(mt.w01d, b1lo, ffma2(mt.w10d, c1lo, fmul2(mt.w11d, d1lo))));
                vhi = ffma2(mt.w00d, a1hi, ffma2(mt.w01d, b1hi, ffma2(mt.w10d, c1hi, fmul2(mt.w11d, d1hi))));
                unpack2(vlo, s0, s1);
                unpack2(vhi, s2, s3);
                sb += 256;
                nbuf[sb]       = s0;
                nbuf[sb +  64] = s1;
                nbuf[sb + 128] = s2;
                nbuf[sb + 192] = s3;
            }
        }
        __syncthreads();
    }

    // Final tap (k=8): GEMM only, reads buf 0 (written during k=7).
    {
        unsigned sbase = smem_u + px_base * 4;
        const float* wk = g_Wt + 8*4096 + o_base;
        #pragma unroll 4
        for (int c = 0; c < 64; c++) {
            u64 s01, s23, s45, s67;
            lds128_2(sbase + c*256,      s01, s23);
            lds128_2(sbase + c*256 + 16, s45, s67);
            u64 wpa, wpb, wpc, wpd;
            ldg128_2(wk + c*64,     wpa, wpb);
            ldg128_2(wk + c*64 + 4, wpc, wpd);
            float w_[8];
            unpack2(wpa, w_[0], w_[1]);
            unpack2(wpb, w_[2], w_[3]);
            unpack2(wpc, w_[4], w_[5]);
            unpack2(wpd, w_[6], w_[7]);
            #pragma unroll
            for (int oi = 0; oi < 8; oi++) {
                u64 wd = dup2(w_[oi]);
                acc[oi][0] = ffma2(wd, s01, acc[oi][0]);
                acc[oi][1] = ffma2(wd, s23, acc[oi][1]);
                acc[oi][2] = ffma2(wd, s45, acc[oi][2]);
                acc[oi][3] = ffma2(wd, s67, acc[oi][3]);
            }
        }
    }

    #pragma unroll
    for (int oi = 0; oi < 8; oi++) {
        float bv = __ldg(bias + o_base + oi);
        float r[8];
        unpack2(acc[oi][0], r[0], r[1]);
        unpack2(acc[oi][1], r[2], r[3]);
        unpack2(acc[oi][2], r[4], r[5]);
        unpack2(acc[oi][3], r[6], r[7]);
        float* ob = out + (((b*64 + o_base + oi)*NH + h)*NW) + w0 + px_base;
        *(float4*)ob       = make_float4(r[0]+bv, r[1]+bv, r[2]+bv, r[3]+bv);
        *(float4*)(ob + 4) = make_float4(r[4]+bv, r[5]+bv, r[6]+bv, r[7]+bv);
    }
}

// ---------------------------------------------------------------------------
extern "C" void kernel_launch(void* const* d_in, const int* in_sizes, int n_in,
                              void* d_out, int out_size) {
    const float* x         = (const float*)d_in[0];
    const float* weight    = (const float*)d_in[1];
    const float* bias      = (const float*)d_in[2];
    const float* om_weight = (const float*)d_in[3];
    const float* om_bias   = (const float*)d_in[4];
    float* out = (float*)d_out;

    cudaFuncSetAttribute(k_offsets, cudaFuncAttributeMaxDynamicSharedMemorySize, 9*64*28*4);

    k_transpose<<<2048, 256>>>(x);
    k_reorg<<<144, 256>>>(weight, om_weight);
    k_offsets<<<128, 256, 9*64*28*4>>>(om_bias);
    k_main<<<1024, 64>>>(bias, out);
}

// round 10
// speedup vs baseline: 1.1740x; 1.0036x over previous
#include <cuda_runtime.h>
#include <math.h>
#include <stdint.h>

#define NB 4
#define NC 64
#define NO 64
#define NH 128
#define NW 128
#define HW (NH*NW)

typedef unsigned long long u64;

// ---- f32x2 packed helpers (sm_100+) ---------------------------------------
__device__ __forceinline__ u64 pack2(float lo, float hi) {
    u64 r; asm("mov.b64 %0, {%1, %2};" : "=l"(r) : "f"(lo), "f"(hi)); return r;
}
__device__ __forceinline__ u64 dup2(float v) {
    u64 r; asm("mov.b64 %0, {%1, %1};" : "=l"(r) : "f"(v)); return r;
}
__device__ __forceinline__ void unpack2(u64 p, float& lo, float& hi) {
    asm("mov.b64 {%0, %1}, %2;" : "=f"(lo), "=f"(hi) : "l"(p));
}
__device__ __forceinline__ u64 ffma2(u64 a, u64 b, u64 c) {
    u64 d; asm("fma.rn.f32x2 %0, %1, %2, %3;" : "=l"(d) : "l"(a), "l"(b), "l"(c)); return d;
}
__device__ __forceinline__ u64 fmul2(u64 a, u64 b) {
    u64 d; asm("mul.rn.f32x2 %0, %1, %2;" : "=l"(d) : "l"(a), "l"(b)); return d;
}
__device__ __forceinline__ void ldg128_2(const void* p, u64& lo, u64& hi) {
    asm("ld.global.nc.v2.u64 {%0,%1}, [%2];" : "=l"(lo), "=l"(hi) : "l"(p));
}
__device__ __forceinline__ void lds128_2(unsigned addr, u64& lo, u64& hi) {
    asm("ld.shared.v2.u64 {%0,%1}, [%2];" : "=l"(lo), "=l"(hi) : "r"(addr));
}

// Scratch (static device globals — no allocation)
__device__ float g_xT[NB*16*HW*4];      // x repacked: [b][c/4][h][w][4]
__device__ float g_py[NB*9*HW];         // sample y coord per (b,k,h,w)
__device__ float g_px[NB*9*HW];         // sample x coord
__device__ float g_ms[NB*9*HW];         // sigmoid(mask)
__device__ float g_Wt[9*64*64];         // weight repacked: [k][c][o]
__device__ float g_omwT[9*64*28];       // om_weight repacked: [tap][c][j(pad28)]

// ---------------------------------------------------------------------------
// Kernel 0: NCHW -> [b][c/4][h][w][4] repack (coalesced via smem tile)
// ---------------------------------------------------------------------------
__global__ void __launch_bounds__(256) k_transpose(const float* __restrict__ x) {
    __shared__ float ts[64][33];
    int blk = blockIdx.x;
    int wc = blk & 3;
    int h  = (blk >> 2) & 127;
    int b  = blk >> 9;
    int w0 = wc * 32;
    int t = threadIdx.x;
    #pragma unroll
    for (int i = 0; i < 8; i++) {
        int idx = i * 256 + t;
        int c = idx >> 5, w = idx & 31;
        ts[c][w] = x[((b*64 + c)*NH + h)*NW + w0 + w];
    }
    __syncthreads();
    #pragma unroll
    for (int i = 0; i < 8; i++) {
        int idx = i * 256 + t;
        int comp = idx & 3, w = (idx >> 2) & 31, cg = idx >> 7;
        g_xT[((((b*16 + cg)*NH + h)*NW + w0 + w) << 2) + comp] = ts[cg*4 + comp][w];
    }
}

// ---------------------------------------------------------------------------
// Kernel R: weight reorganizations.
// ---------------------------------------------------------------------------
__global__ void __launch_bounds__(256) k_reorg(const float* __restrict__ wgt,
                                               const float* __restrict__ omw) {
    int i = blockIdx.x * 256 + threadIdx.x;
    if (i < 9*64*64) {              // g_Wt[k][c][o] = weight[o][c][k]
        int o = i & 63, c = (i >> 6) & 63, k = i >> 12;
        g_Wt[i] = wgt[(o*64 + c)*9 + k];
    }
    if (i < 9*64*28) {              // g_omwT[tap][c][j] = om_weight[j][c][tap]
        int j = i % 28;
        int c = (i / 28) & 63;
        int tap = i / (28*64);
        g_omwT[i] = (j < 27) ? omw[(j*64 + c)*9 + tap] : 0.f;
    }
}

// ---------------------------------------------------------------------------
// Kernel 1: offset/mask conv (64 -> 27ch 3x3), f32x2, R1 launch shape
// (128 blocks x 256 threads, 2 horizontally adjacent pixels per thread).
// ---------------------------------------------------------------------------
__global__ void __launch_bounds__(256) k_offsets(const float* __restrict__ om_bias) {
    extern __shared__ float wsm[];      // [tap][c][28]
    int t = threadIdx.x;
    for (int i = t; i < 9*64*28; i += 256) wsm[i] = g_omwT[i];
    __syncthreads();
    unsigned wsm_u = (unsigned)__cvta_generic_to_shared(wsm);

    int lin = blockIdx.x * 256 + t;     // 0..32767 (pixel pairs)
    int w0 = (lin & 63) * 2;
    int h  = (lin >> 6) & 127;
    int b  = lin >> 13;

    u64 acc0[14], acc1[14];             // [j4*2 + half] : j pairs
    #pragma unroll
    for (int j4 = 0; j4 < 7; j4++) {
        float bv[4];
        #pragma unroll
        for (int q = 0; q < 4; q++) {
            int j = j4*4 + q;
            bv[q] = (j < 27) ? __ldg(om_bias + j) : 0.f;
        }
        acc0[j4*2]   = pack2(bv[0], bv[1]);
        acc0[j4*2+1] = pack2(bv[2], bv[3]);
        acc1[j4*2]   = acc0[j4*2];
        acc1[j4*2+1] = acc0[j4*2+1];
    }

    #pragma unroll
    for (int tap = 0; tap < 9; tap++) {
        int ny  = h + tap/3 - 1;
        int nx0 = w0 + tap%3 - 1;
        bool vy = (ny >= 0) && (ny < NH);
        bool v0 = vy && (nx0 >= 0) && (nx0 < NW);
        bool v1 = vy && (nx0 + 1 >= 0) && (nx0 + 1 < NW);
        #pragma unroll
        for (int cg = 0; cg < 16; cg++) {
            float4 p0 = make_float4(0.f,0.f,0.f,0.f);
            float4 p1 = make_float4(0.f,0.f,0.f,0.f);
            if (v0) p0 = *(const float4*)(g_xT + ((((b*16 + cg)*NH + ny)*NW + nx0) << 2));
            if (v1) p1 = *(const float4*)(g_xT + ((((b*16 + cg)*NH + ny)*NW + nx0 + 1) << 2));
            float p0a[4], p1a[4];
            *(float4*)p0a = p0; *(float4*)p1a = p1;
            #pragma unroll
            for (int ci = 0; ci < 4; ci++) {
                u64 a0d = dup2(p0a[ci]);
                u64 a1d = dup2(p1a[ci]);
                unsigned wa = wsm_u + ((tap*64 + cg*4 + ci)*28) * 4;
                #pragma unroll
                for (int j4 = 0; j4 < 7; j4++) {
                    u64 wlo, whi;
                    lds128_2(wa + j4*16, wlo, whi);
                    acc0[j4*2]   = ffma2(wlo, a0d, acc0[j4*2]);
                    acc0[j4*2+1] = ffma2(whi, a0d, acc0[j4*2+1]);
                    acc1[j4*2]   = ffma2(wlo, a1d, acc1[j4*2]);
                    acc1[j4*2+1] = ffma2(whi, a1d, acc1[j4*2+1]);
                }
            }
        }
    }

    float o0[28], o1[28];
    #pragma unroll
    for (int j4 = 0; j4 < 7; j4++) {
        unpack2(acc0[j4*2],   o0[j4*4],   o0[j4*4+1]);
        unpack2(acc0[j4*2+1], o0[j4*4+2], o0[j4*4+3]);
        unpack2(acc1[j4*2],   o1[j4*4],   o1[j4*4+1]);
        unpack2(acc1[j4*2+1], o1[j4*4+2], o1[j4*4+3]);
    }

    #pragma unroll
    for (int k = 0; k < 9; k++) {
        int off = ((b*9 + k)*NH + h)*NW + w0;
        float ky = (float)(k/3), kx = (float)(k%3);
        g_py[off]     = o0[2*k]   + ky + (float)(h - 1);
        g_py[off + 1] = o1[2*k]   + ky + (float)(h - 1);
        g_px[off]     = o0[2*k+1] + kx + (float)(w0 - 1);
        g_px[off + 1] = o1[2*k+1] + kx + (float)(w0);
        g_ms[off]     = 1.f / (1.f + expf(-o0[18+k]));
        g_ms[off + 1] = 1.f / (1.f + expf(-o1[18+k]));
    }
}

// ---------------------------------------------------------------------------
// Meta for one tap (per thread: one pixel).
// ---------------------------------------------------------------------------
struct Meta {
    u64 w00d, w01d, w10d, w11d;
    int i00, i01, i10, i11;
};
__device__ __forceinline__ Meta make_meta(int mi) {
    Meta mt;
    float py  = __ldg(g_py + mi);
    float pxx = __ldg(g_px + mi);
    float m   = __ldg(g_ms + mi);
    float y0f = floorf(py), x0f = floorf(pxx);
    float wy = py - y0f, wx = pxx - x0f;
    bool vy0 = (y0f >=  0.f) && (y0f <= 127.f);
    bool vy1 = (y0f >= -1.f) && (y0f <= 126.f);
    bool vx0 = (x0f >=  0.f) && (x0f <= 127.f);
    bool vx1 = (x0f >= -1.f) && (x0f <= 126.f);
    int iy0 = (int)fminf(fmaxf(y0f,       0.f), 127.f);
    int iy1 = (int)fminf(fmaxf(y0f + 1.f, 0.f), 127.f);
    int ix0 = (int)fminf(fmaxf(x0f,       0.f), 127.f);
    int ix1 = (int)fminf(fmaxf(x0f + 1.f, 0.f), 127.f);
    mt.w00d = dup2((1.f-wy)*(1.f-wx) * ((vy0 && vx0) ? m : 0.f));
    mt.w01d = dup2((1.f-wy)*wx       * ((vy0 && vx1) ? m : 0.f));
    mt.w10d = dup2(wy*(1.f-wx)       * ((vy1 && vx0) ? m : 0.f));
    mt.w11d = dup2(wy*wx             * ((vy1 && vx1) ? m : 0.f));
    mt.i00 = iy0*NW + ix0; mt.i01 = iy0*NW + ix1;
    mt.i10 = iy1*NW + ix0; mt.i11 = iy1*NW + ix1;
    return mt;
}

// Simple full-tap gather (prologue only).
__device__ __forceinline__ void gather_tap(const char* __restrict__ xb,
                                           int mi, int px,
                                           float* __restrict__ buf) {
    Meta mt = make_meta(mi);
    #pragma unroll 4
    for (int cg = 0; cg < 16; cg++) {
        const char* cb = xb + ((size_t)cg*HW << 4);
        u64 Alo, Ahi, Blo, Bhi, Clo, Chi, Dlo, Dhi;
        ldg128_2(cb + ((size_t)mt.i00 << 4), Alo, Ahi);
        ldg128_2(cb + ((size_t)mt.i01 << 4), Blo, Bhi);
        ldg128_2(cb + ((size_t)mt.i10 << 4), Clo, Chi);
        ldg128_2(cb + ((size_t)mt.i11 << 4), Dlo, Dhi);
        u64 vlo = ffma2(mt.w00d, Alo, ffma2(mt.w01d, Blo, ffma2(mt.w10d, Clo, fmul2(mt.w11d, Dlo))));
        u64 vhi = ffma2(mt.w00d, Ahi, ffma2(mt.w01d, Bhi, ffma2(mt.w10d, Chi, fmul2(mt.w11d, Dhi))));
        float s0, s1, s2, s3;
        unpack2(vlo, s0, s1);
        unpack2(vhi, s2, s3);
        int sb = (cg*4)*64 + px;
        buf[sb]       = s0;
        buf[sb +  64] = s1;
        buf[sb + 128] = s2;
        buf[sb + 192] = s3;
    }
}

// ---------------------------------------------------------------------------
// Kernel 2: bilinear sampling + output GEMM, chunk-interleaved pipeline.
// 64-thread CTAs, one per (b,h,half): 1024 blocks, 32KB smem, 6 CTAs/SM.
// Thread tile 8px x 8o. Per chunk q: issue next-tap corner LDGs for 2 cg,
// run 8 GEMM c-iters (covers load latency), then blend+STS.
// ---------------------------------------------------------------------------
__global__ void __launch_bounds__(64, 6) k_main(const float* __restrict__ bias,
                                                float* __restrict__ out) {
    __shared__ float ssamp[2][64*64];   // 32 KB
    unsigned smem_u = (unsigned)__cvta_generic_to_shared(ssamp);
    int t = threadIdx.x;                // 0..63
    int blk = blockIdx.x;
    int half = blk & 1;
    int h = (blk >> 1) & 127;
    int b = blk >> 8;
    int w0 = half * 64;

    int px = t;                         // gather: one pixel per thread
    int px_base = (t & 7) * 8;          // GEMM: 8 pixels
    int o_base  = (t >> 3) * 8;         // GEMM: 8 outputs

    const char* xb = (const char*)g_xT + (((size_t)(b*16))*HW << 4);
    int offm = (b*9)*HW + h*NW + w0 + px;

    u64 acc[8][4];
    u64 z = dup2(0.f);
    #pragma unroll
    for (int i = 0; i < 8; i++)
        #pragma unroll
        for (int j = 0; j < 4; j++) acc[i][j] = z;

    // prologue: gather tap 0 into buf 0
    gather_tap(xb, offm, px, ssamp[0]);
    __syncthreads();

    #pragma unroll 1
    for (int k = 0; k < 8; k++) {
        unsigned sbase = smem_u + ((k & 1) * 4096 + px_base) * 4;
        const float* wk = g_Wt + k*4096 + o_base;
        float* nbuf = ssamp[(k + 1) & 1];
        Meta mt = make_meta(offm + (k+1)*HW);   // next tap's meta

        #pragma unroll
        for (int q = 0; q < 8; q++) {
            // --- issue next-tap corner loads for cg pair (2q, 2q+1) ---
            const char* cb0 = xb + ((size_t)(2*q)*HW << 4);
            const char* cb1 = xb + ((size_t)(2*q + 1)*HW << 4);
            u64 a0lo, a0hi, b0lo, b0hi, c0lo, c0hi, d0lo, d0hi;
            u64 a1lo, a1hi, b1lo, b1hi, c1lo, c1hi, d1lo, d1hi;
            ldg128_2(cb0 + ((size_t)mt.i00 << 4), a0lo, a0hi);
            ldg128_2(cb0 + ((size_t)mt.i01 << 4), b0lo, b0hi);
            ldg128_2(cb0 + ((size_t)mt.i10 << 4), c0lo, c0hi);
            ldg128_2(cb0 + ((size_t)mt.i11 << 4), d0lo, d0hi);
            ldg128_2(cb1 + ((size_t)mt.i00 << 4), a1lo, a1hi);
            ldg128_2(cb1 + ((size_t)mt.i01 << 4), b1lo, b1hi);
            ldg128_2(cb1 + ((size_t)mt.i10 << 4), c1lo, c1hi);
            ldg128_2(cb1 + ((size_t)mt.i11 << 4), d1lo, d1hi);

            // --- GEMM 8 c-iters on current tap (covers load latency) ---
            #pragma unroll
            for (int ci = 0; ci < 8; ci++) {
                int c = q*8 + ci;
                u64 s01, s23, s45, s67;
                lds128_2(sbase + c*256,      s01, s23);
                lds128_2(sbase + c*256 + 16, s45, s67);
                u64 wpa, wpb, wpc, wpd;
                ldg128_2(wk + c*64,     wpa, wpb);
                ldg128_2(wk + c*64 + 4, wpc, wpd);
                float w_[8];
                unpack2(wpa, w_[0], w_[1]);
                unpack2(wpb, w_[2], w_[3]);
                unpack2(wpc, w_[4], w_[5]);
                unpack2(wpd, w_[6], w_[7]);
                #pragma unroll
                for (int oi = 0; oi < 8; oi++) {
                    u64 wd = dup2(w_[oi]);
                    acc[oi][0] = ffma2(wd, s01, acc[oi][0]);
                    acc[oi][1] = ffma2(wd, s23, acc[oi][1]);
                    acc[oi][2] = ffma2(wd, s45, acc[oi][2]);
                    acc[oi][3] = ffma2(wd, s67, acc[oi][3]);
                }
            }

            // --- blend + store next-tap data (loads have landed) ---
            {
                u64 vlo = ffma2(mt.w00d, a0lo, ffma2(mt.w01d, b0lo, ffma2(mt.w10d, c0lo, fmul2(mt.w11d, d0lo))));
                u64 vhi = ffma2(mt.w00d, a0hi, ffma2(mt.w01d, b0hi, ffma2(mt.w10d, c0hi, fmul2(mt.w11d, d0hi))));
                float s0, s1, s2, s3;
                unpack2(vlo, s0, s1);
                unpack2(vhi, s2, s3);
                int sb = (2*q*4)*64 + px;
                nbuf[sb]       = s0;
                nbuf[sb +  64] = s1;
                nbuf[sb + 128] = s2;
                nbuf[sb + 192] = s3;
                vlo = ffma2(mt.w00d, a1lo, ffma2(mt.w01d, b1lo, ffma2(mt.w10d, c1lo, fmul2(mt.w11d, d1lo))));
                vhi = ffma2(mt.w00d, a1hi, ffma2(mt.w01d, b1hi, ffma2(mt.w10d, c1hi, fmul2(mt.w11d, d1hi))));
                unpack2(vlo, s0, s1);
                unpack2(vhi, s2, s3);
                sb += 256;
                nbuf[sb]       = s0;
                nbuf[sb +  64] = s1;
                nbuf[sb + 128] = s2;
                nbuf[sb + 192] = s3;
            }
        }
        __syncthreads();
    }

    // Final tap (k=8): GEMM only, reads buf 0 (written during k=7).
    {
        unsigned sbase = smem_u + px_base * 4;
        const float* wk = g_Wt + 8*4096 + o_base;
        #pragma unroll 4
        for (int c = 0; c < 64; c++) {
            u64 s01, s23, s45, s67;
            lds128_2(sbase + c*256,      s01, s23);
            lds128_2(sbase + c*256 + 16, s45, s67);
            u64 wpa, wpb, wpc, wpd;
            ldg128_2(wk + c*64,     wpa, wpb);
            ldg128_2(wk + c*64 + 4, wpc, wpd);
            float w_[8];
            unpack2(wpa, w_[0], w_[1]);
            unpack2(wpb, w_[2], w_[3]);
            unpack2(wpc, w_[4], w_[5]);
            unpack2(wpd, w_[6], w_[7]);
            #pragma unroll
            for (int oi = 0; oi < 8; oi++) {
                u64 wd = dup2(w_[oi]);
                acc[oi][0] = ffma2(wd, s01, acc[oi][0]);
                acc[oi][1] = ffma2(wd, s23, acc[oi][1]);
                acc[oi][2] = ffma2(wd, s45, acc[oi][2]);
                acc[oi][3] = ffma2(wd, s67, acc[oi][3]);
            }
        }
    }

    #pragma unroll
    for (int oi = 0; oi < 8; oi++) {
        float bv = __ldg(bias + o_base + oi);
        float r[8];
        unpack2(acc[oi][0], r[0], r[1]);
        unpack2(acc[oi][1], r[2], r[3]);
        unpack2(acc[oi][2], r[4], r[5]);
        unpack2(acc[oi][3], r[6], r[7]);
        float* ob = out + (((b*64 + o_base + oi)*NH + h)*NW) + w0 + px_base;
        *(float4*)ob       = make_float4(r[0]+bv, r[1]+bv, r[2]+bv, r[3]+bv);
        *(float4*)(ob + 4) = make_float4(r[4]+bv, r[5]+bv, r[6]+bv, r[7]+bv);
    }
}

// ---------------------------------------------------------------------------
extern "C" void kernel_launch(void* const* d_in, const int* in_sizes, int n_in,
                              void* d_out, int out_size) {
    const float* x         = (const float*)d_in[0];
    const float* weight    = (const float*)d_in[1];
    const float* bias      = (const float*)d_in[2];
    const float* om_weight = (const float*)d_in[3];
    const float* om_bias   = (const float*)d_in[4];
    float* out = (float*)d_out;

    cudaFuncSetAttribute(k_offsets, cudaFuncAttributeMaxDynamicSharedMemorySize, 9*64*28*4);

    k_transpose<<<2048, 256>>>(x);
    k_reorg<<<144, 256>>>(weight, om_weight);
    k_offsets<<<128, 256, 9*64*28*4>>>(om_bias);
    k_main<<<1024, 64>>>(bias, out);
}

// round 11
// speedup vs baseline: 1.1784x; 1.0037x over previous
#include <cuda_runtime.h>
#include <math.h>
#include <stdint.h>

#define NB 4
#define NC 64
#define NO 64
#define NH 128
#define NW 128
#define HW (NH*NW)

typedef unsigned long long u64;

// ---- f32x2 packed helpers (sm_100+) ---------------------------------------
__device__ __forceinline__ u64 pack2(float lo, float hi) {
    u64 r; asm("mov.b64 %0, {%1, %2};" : "=l"(r) : "f"(lo), "f"(hi)); return r;
}
__device__ __forceinline__ u64 dup2(float v) {
    u64 r; asm("mov.b64 %0, {%1, %1};" : "=l"(r) : "f"(v)); return r;
}
__device__ __forceinline__ void unpack2(u64 p, float& lo, float& hi) {
    asm("mov.b64 {%0, %1}, %2;" : "=f"(lo), "=f"(hi) : "l"(p));
}
__device__ __forceinline__ u64 ffma2(u64 a, u64 b, u64 c) {
    u64 d; asm("fma.rn.f32x2 %0, %1, %2, %3;" : "=l"(d) : "l"(a), "l"(b), "l"(c)); return d;
}
__device__ __forceinline__ u64 fmul2(u64 a, u64 b) {
    u64 d; asm("mul.rn.f32x2 %0, %1, %2;" : "=l"(d) : "l"(a), "l"(b)); return d;
}
__device__ __forceinline__ void ldg128_2(const void* p, u64& lo, u64& hi) {
    asm("ld.global.nc.v2.u64 {%0,%1}, [%2];" : "=l"(lo), "=l"(hi) : "l"(p));
}
__device__ __forceinline__ void lds128_2(unsigned addr, u64& lo, u64& hi) {
    asm("ld.shared.v2.u64 {%0,%1}, [%2];" : "=l"(lo), "=l"(hi) : "r"(addr));
}

// Scratch (static device globals — no allocation)
__device__ float g_xT[NB*16*HW*4];      // x repacked: [b][c/4][h][w][4]
__device__ float g_Wt[9*64*64];         // weight repacked: [k][c][o]
__device__ float g_omwT[9*64*28];       // om_weight repacked: [tap][c][j(pad28)]

// ---------------------------------------------------------------------------
// Kernel P: fused prep.
//  blocks [0, 2048): NCHW -> [b][c/4][h][w][4] repack (coalesced via smem)
//  blocks [2048, 2192): weight reorganizations
// ---------------------------------------------------------------------------
__global__ void __launch_bounds__(256) k_prep(const float* __restrict__ x,
                                              const float* __restrict__ wgt,
                                              const float* __restrict__ omw) {
    __shared__ float ts[64][33];
    int blk = blockIdx.x;
    int t = threadIdx.x;
    if (blk < 2048) {
        int wc = blk & 3;
        int h  = (blk >> 2) & 127;
        int b  = blk >> 9;
        int w0 = wc * 32;
        #pragma unroll
        for (int i = 0; i < 8; i++) {
            int idx = i * 256 + t;
            int c = idx >> 5, w = idx & 31;
            ts[c][w] = x[((b*64 + c)*NH + h)*NW + w0 + w];
        }
        __syncthreads();
        #pragma unroll
        for (int i = 0; i < 8; i++) {
            int idx = i * 256 + t;
            int comp = idx & 3, w = (idx >> 2) & 31, cg = idx >> 7;
            g_xT[((((b*16 + cg)*NH + h)*NW + w0 + w) << 2) + comp] = ts[cg*4 + comp][w];
        }
    } else {
        int i = (blk - 2048) * 256 + t;     // 0..36863
        if (i < 9*64*64) {                  // g_Wt[k][c][o] = weight[o][c][k]
            int o = i & 63, c = (i >> 6) & 63, k = i >> 12;
            g_Wt[i] = wgt[(o*64 + c)*9 + k];
        }
        if (i < 9*64*28) {                  // g_omwT[tap][c][j] = om_weight[j][c][tap]
            int j = i % 28;
            int c = (i / 28) & 63;
            int tap = i / (28*64);
            g_omwT[i] = (j < 27) ? omw[(j*64 + c)*9 + tap] : 0.f;
        }
    }
}

// ---------------------------------------------------------------------------
// Meta for one tap (bilinear corner weights + clamped indices).
// ---------------------------------------------------------------------------
struct Meta {
    u64 w00d, w01d, w10d, w11d;
    int i00, i01, i10, i11;
};
__device__ __forceinline__ Meta make_meta_v(float py, float pxx, float m) {
    Meta mt;
    float y0f = floorf(py), x0f = floorf(pxx);
    float wy = py - y0f, wx = pxx - x0f;
    bool vy0 = (y0f >=  0.f) && (y0f <= 127.f);
    bool vy1 = (y0f >= -1.f) && (y0f <= 126.f);
    bool vx0 = (x0f >=  0.f) && (x0f <= 127.f);
    bool vx1 = (x0f >= -1.f) && (x0f <= 126.f);
    int iy0 = (int)fminf(fmaxf(y0f,       0.f), 127.f);
    int iy1 = (int)fminf(fmaxf(y0f + 1.f, 0.f), 127.f);
    int ix0 = (int)fminf(fmaxf(x0f,       0.f), 127.f);
    int ix1 = (int)fminf(fmaxf(x0f + 1.f, 0.f), 127.f);
    mt.w00d = dup2((1.f-wy)*(1.f-wx) * ((vy0 && vx0) ? m : 0.f));
    mt.w01d = dup2((1.f-wy)*wx       * ((vy0 && vx1) ? m : 0.f));
    mt.w10d = dup2(wy*(1.f-wx)       * ((vy1 && vx0) ? m : 0.f));
    mt.w11d = dup2(wy*wx             * ((vy1 && vx1) ? m : 0.f));
    mt.i00 = iy0*NW + ix0; mt.i01 = iy0*NW + ix1;
    mt.i10 = iy1*NW + ix0; mt.i11 = iy1*NW + ix1;
    return mt;
}

// meta from per-pixel offset-conv results kept in smem soff[j][px]
__device__ __forceinline__ Meta meta_from_soff(const float* soff, int px, int k,
                                               int h, int gw) {
    float py  = soff[(2*k)*64 + px]   + (float)(k/3) + (float)(h - 1);
    float pxx = soff[(2*k+1)*64 + px] + (float)(k%3) + (float)(gw - 1);
    float m   = 1.f / (1.f + expf(-soff[(18+k)*64 + px]));
    return make_meta_v(py, pxx, m);
}

// Simple full-tap gather (prologue only).
__device__ __forceinline__ void gather_tap(const char* __restrict__ xb,
                                           Meta mt, int px,
                                           float* __restrict__ buf) {
    #pragma unroll 4
    for (int cg = 0; cg < 16; cg++) {
        const char* cb = xb + ((size_t)cg*HW << 4);
        u64 Alo, Ahi, Blo, Bhi, Clo, Chi, Dlo, Dhi;
        ldg128_2(cb + ((size_t)mt.i00 << 4), Alo, Ahi);
        ldg128_2(cb + ((size_t)mt.i01 << 4), Blo, Bhi);
        ldg128_2(cb + ((size_t)mt.i10 << 4), Clo, Chi);
        ldg128_2(cb + ((size_t)mt.i11 << 4), Dlo, Dhi);
        u64 vlo = ffma2(mt.w00d, Alo, ffma2(mt.w01d, Blo, ffma2(mt.w10d, Clo, fmul2(mt.w11d, Dlo))));
        u64 vhi = ffma2(mt.w00d, Ahi, ffma2(mt.w01d, Bhi, ffma2(mt.w10d, Chi, fmul2(mt.w11d, Dhi))));
        float s0, s1, s2, s3;
        unpack2(vlo, s0, s1);
        unpack2(vhi, s2, s3);
        int sb = (cg*4)*64 + px;
        buf[sb]       = s0;
        buf[sb +  64] = s1;
        buf[sb + 128] = s2;
        buf[sb + 192] = s3;
    }
}

// ---------------------------------------------------------------------------
// Kernel 2 (fused): offset conv prologue + bilinear sampling + output GEMM.
// 64-thread CTAs, one per (b,h,half): 1024 blocks, ~40KB smem, 5 CTAs/SM.
// ---------------------------------------------------------------------------
__global__ void __launch_bounds__(64, 5) k_main(const float* __restrict__ bias,
                                                const float* __restrict__ om_bias,
                                                float* __restrict__ out) {
    __shared__ float ssamp[2][64*64];   // 32 KB (also staging for om weights)
    __shared__ float soff[28*64];       // 7 KB: per-pixel offset-conv results
    unsigned smem_u = (unsigned)__cvta_generic_to_shared(ssamp);
    int t = threadIdx.x;                // 0..63
    int blk = blockIdx.x;
    int half = blk & 1;
    int h = (blk >> 1) & 127;
    int b = blk >> 8;
    int w0 = half * 64;

    int px = t;                         // one pixel per thread
    int gw = w0 + px;                   // global x coord
    int px_base = (t & 7) * 8;          // GEMM: 8 pixels
    int o_base  = (t >> 3) * 8;         // GEMM: 8 outputs

    const char* xb = (const char*)g_xT + (((size_t)(b*16))*HW << 4);

    // ================= fused offset/mask conv (64 -> 27ch, 3x3) ===========
    {
        float* wst = &ssamp[0][0];      // weight staging (max 4 taps = 28KB)
        u64 oacc[14];
        #pragma unroll
        for (int j2 = 0; j2 < 14; j2++) {
            float b0v = (2*j2   < 27) ? __ldg(om_bias + 2*j2)     : 0.f;
            float b1v = (2*j2+1 < 27) ? __ldg(om_bias + 2*j2 + 1) : 0.f;
            oacc[j2] = pack2(b0v, b1v);
        }
        int tap0 = 0;
        #pragma unroll
        for (int stage = 0; stage < 3; stage++) {
            int nt = (stage == 2) ? 1 : 4;
            // stage nt taps of om weights into smem (448 float4 per tap)
            for (int i = t; i < nt*448; i += 64)
                ((float4*)wst)[i] = ((const float4*)(g_omwT + tap0*64*28))[i];
            __syncthreads();
            for (int tt = 0; tt < nt; tt++) {
                int tap = tap0 + tt;
                int ny = h + tap/3 - 1;
                int nx = gw + tap%3 - 1;
                bool v = (ny >= 0) && (ny < NH) && (nx >= 0) && (nx < NW);
                #pragma unroll 4
                for (int cg = 0; cg < 16; cg++) {
                    float4 p = make_float4(0.f,0.f,0.f,0.f);
                    if (v) p = *(const float4*)(g_xT + ((((b*16 + cg)*NH + ny)*NW + nx) << 2));
                    float pa[4]; *(float4*)pa = p;
                    #pragma unroll
                    for (int ci = 0; ci < 4; ci++) {
                        u64 ad = dup2(pa[ci]);
                        unsigned wa = smem_u + ((tt*64 + cg*4 + ci)*28) * 4;
                        #pragma unroll
                        for (int j4 = 0; j4 < 7; j4++) {
                            u64 wlo, whi;
                            lds128_2(wa + j4*16, wlo, whi);
                            oacc[j4*2]   = ffma2(wlo, ad, oacc[j4*2]);
                            oacc[j4*2+1] = ffma2(whi, ad, oacc[j4*2+1]);
                        }
                    }
                }
            }
            __syncthreads();            // guard wst overwrite / ssamp reuse
            tap0 += nt;
        }
        #pragma unroll
        for (int j2 = 0; j2 < 14; j2++) {
            float lo, hi; unpack2(oacc[j2], lo, hi);
            soff[(2*j2)*64 + px]     = lo;      // own-pixel; read by self only
            soff[(2*j2 + 1)*64 + px] = hi;
        }
    }

    // ================= gather + GEMM pipeline ==============================
    u64 acc[8][4];
    u64 z = dup2(0.f);
    #pragma unroll
    for (int i = 0; i < 8; i++)
        #pragma unroll
        for (int j = 0; j < 4; j++) acc[i][j] = z;

    // prologue: gather tap 0 into buf 0
    gather_tap(xb, meta_from_soff(soff, px, 0, h, gw), px, ssamp[0]);
    __syncthreads();

    #pragma unroll 1
    for (int k = 0; k < 8; k++) {
        unsigned sbase = smem_u + ((k & 1) * 4096 + px_base) * 4;
        const float* wk = g_Wt + k*4096 + o_base;
        float* nbuf = ssamp[(k + 1) & 1];
        Meta mt = meta_from_soff(soff, px, k + 1, h, gw);   // next tap's meta

        #pragma unroll
        for (int q = 0; q < 8; q++) {
            // --- issue next-tap corner loads for cg pair (2q, 2q+1) ---
            const char* cb0 = xb + ((size_t)(2*q)*HW << 4);
            const char* cb1 = xb + ((size_t)(2*q + 1)*HW << 4);
            u64 a0lo, a0hi, b0lo, b0hi, c0lo, c0hi, d0lo, d0hi;
            u64 a1lo, a1hi, b1lo, b1hi, c1lo, c1hi, d1lo, d1hi;
            ldg128_2(cb0 + ((size_t)mt.i00 << 4), a0lo, a0hi);
            ldg128_2(cb0 + ((size_t)mt.i01 << 4), b0lo, b0hi);
            ldg128_2(cb0 + ((size_t)mt.i10 << 4), c0lo, c0hi);
            ldg128_2(cb0 + ((size_t)mt.i11 << 4), d0lo, d0hi);
            ldg128_2(cb1 + ((size_t)mt.i00 << 4), a1lo, a1hi);
            ldg128_2(cb1 + ((size_t)mt.i01 << 4), b1lo, b1hi);
            ldg128_2(cb1 + ((size_t)mt.i10 << 4), c1lo, c1hi);
            ldg128_2(cb1 + ((size_t)mt.i11 << 4), d1lo, d1hi);

            // --- GEMM 8 c-iters on current tap (covers load latency) ---
            #pragma unroll
            for (int ci = 0; ci < 8; ci++) {
                int c = q*8 + ci;
                u64 s01, s23, s45, s67;
                lds128_2(sbase + c*256,      s01, s23);
                lds128_2(sbase + c*256 + 16, s45, s67);
                u64 wpa, wpb, wpc, wpd;
                ldg128_2(wk + c*64,     wpa, wpb);
                ldg128_2(wk + c*64 + 4, wpc, wpd);
                float w_[8];
                unpack2(wpa, w_[0], w_[1]);
                unpack2(wpb, w_[2], w_[3]);
                unpack2(wpc, w_[4], w_[5]);
                unpack2(wpd, w_[6], w_[7]);
                #pragma unroll
                for (int oi = 0; oi < 8; oi++) {
                    u64 wd = dup2(w_[oi]);
                    acc[oi][0] = ffma2(wd, s01, acc[oi][0]);
                    acc[oi][1] = ffma2(wd, s23, acc[oi][1]);
                    acc[oi][2] = ffma2(wd, s45, acc[oi][2]);
                    acc[oi][3] = ffma2(wd, s67, acc[oi][3]);
                }
            }

            // --- blend + store next-tap data (loads have landed) ---
            {
                u64 vlo = ffma2(mt.w00d, a0lo, ffma2(mt.w01d, b0lo, ffma2(mt.w10d, c0lo, fmul2(mt.w11d, d0lo))));
                u64 vhi = ffma2(mt.w00d, a0hi, ffma2(mt.w01d, b0hi, ffma2(mt.w10d, c0hi, fmul2(mt.w11d, d0hi))));
                float s0, s1, s2, s3;
                unpack2(vlo, s0, s1);
                unpack2(vhi, s2, s3);
                int sb = (2*q*4)*64 + px;
                nbuf[sb]       = s0;
                nbuf[sb +  64] = s1;
                nbuf[sb + 128] = s2;
                nbuf[sb + 192] = s3;
                vlo = ffma2(mt.w00d, a1lo, ffma2(mt.w01d, b1lo, ffma2(mt.w10d, c1lo, fmul2(mt.w11d, d1lo))));
                vhi = ffma2(mt.w00d, a1hi, ffma2(mt.w01d, b1hi, ffma2(mt.w10d, c1hi, fmul2(mt.w11d, d1hi))));
                unpack2(vlo, s0, s1);
                unpack2(vhi, s2, s3);
                sb += 256;
                nbuf[sb]       = s0;
                nbuf[sb +  64] = s1;
                nbuf[sb + 128] = s2;
                nbuf[sb + 192] = s3;
            }
        }
        __syncthreads();
    }

    // Final tap (k=8): GEMM only, reads buf 0 (written during k=7).
    {
        unsigned sbase = smem_u + px_base * 4;
        const float* wk = g_Wt + 8*4096 + o_base;
        #pragma unroll 4
        for (int c = 0; c < 64; c++) {
            u64 s01, s23, s45, s67;
            lds128_2(sbase + c*256,      s01, s23);
            lds128_2(sbase + c*256 + 16, s45, s67);
            u64 wpa, wpb, wpc, wpd;
            ldg128_2(wk + c*64,     wpa, wpb);
            ldg128_2(wk + c*64 + 4, wpc, wpd);
            float w_[8];
            unpack2(wpa, w_[0], w_[1]);
            unpack2(wpb, w_[2], w_[3]);
            unpack2(wpc, w_[4], w_[5]);
            unpack2(wpd, w_[6], w_[7]);
            #pragma unroll
            for (int oi = 0; oi < 8; oi++) {
                u64 wd = dup2(w_[oi]);
                acc[oi][0] = ffma2(wd, s01, acc[oi][0]);
                acc[oi][1] = ffma2(wd, s23, acc[oi][1]);
                acc[oi][2] = ffma2(wd, s45, acc[oi][2]);
                acc[oi][3] = ffma2(wd, s67, acc[oi][3]);
            }
        }
    }

    #pragma unroll
    for (int oi = 0; oi < 8; oi++) {
        float bv = __ldg(bias + o_base + oi);
        float r[8];
        unpack2(acc[oi][0], r[0], r[1]);
        unpack2(acc[oi][1], r[2], r[3]);
        unpack2(acc[oi][2], r[4], r[5]);
        unpack2(acc[oi][3], r[6], r[7]);
        float* ob = out + (((b*64 + o_base + oi)*NH + h)*NW) + w0 + px_base;
        *(float4*)ob       = make_float4(r[0]+bv, r[1]+bv, r[2]+bv, r[3]+bv);
        *(float4*)(ob + 4) = make_float4(r[4]+bv, r[5]+bv, r[6]+bv, r[7]+bv);
    }
}

// ---------------------------------------------------------------------------
extern "C" void kernel_launch(void* const* d_in, const int* in_sizes, int n_in,
                              void* d_out, int out_size) {
    const float* x         = (const float*)d_in[0];
    const float* weight    = (const float*)d_in[1];
    const float* bias      = (const float*)d_in[2];
    const float* om_weight = (const float*)d_in[3];
    const float* om_bias   = (const float*)d_in[4];
    float* out = (float*)d_out;

    k_prep<<<2192, 256>>>(x, weight, om_weight);
    k_main<<<1024, 64>>>(bias, om_bias, out);
}